// round 1
// baseline (speedup 1.0000x reference)
#include <cuda_runtime.h>
#include <math.h>

#define BB 64
#define NN 1024
#define SS 64
#define DD 768
#define HH 256
#define KEEP 96
#define MM (BB*NN)

// scratch (no allocations allowed)
__device__ float g_ctxh[BB*HH];     // ctx @ W1_text + b1, per batch
__device__ float g_scores[MM];
__device__ int   g_topk[BB*KEEP];

// ---------- f32x2 helpers (sm_103a packed fp32 FMA, PTX-only) ----------
__device__ __forceinline__ unsigned long long pack2(float x) {
    unsigned long long r;
    asm("mov.b64 %0, {%1, %1};" : "=l"(r) : "f"(x));
    return r;
}
__device__ __forceinline__ void fma2(unsigned long long& d, unsigned long long a, unsigned long long b) {
    asm("fma.rn.f32x2 %0, %1, %2, %0;" : "+l"(d) : "l"(a), "l"(b));
}
__device__ __forceinline__ float2 unpack2(unsigned long long v) {
    float2 r;
    asm("mov.b64 {%0, %1}, %2;" : "=f"(r.x), "=f"(r.y) : "l"(v));
    return r;
}

// ---------- Kernel 1: per-batch text mean-pool + text-half of layer 1 ----------
__global__ __launch_bounds__(256) void ctx_kernel(
    const float* __restrict__ text, const float* __restrict__ W1,
    const float* __restrict__ b1)
{
    __shared__ float tm[DD];
    int b = blockIdx.x, tid = threadIdx.x;
    for (int d = tid; d < DD; d += 256) {
        const float* p = text + (size_t)b * SS * DD + d;
        float s = 0.f;
        #pragma unroll 8
        for (int j = 0; j < SS; ++j) s += p[(size_t)j * DD];
        tm[d] = s * (1.0f / SS);
    }
    __syncthreads();
    int h = tid;                       // 256 threads = 256 hidden units
    float acc = b1[h];
    const float* w = W1 + (size_t)DD * HH + h;   // text rows start at d=768
    #pragma unroll 8
    for (int d = 0; d < DD; ++d) acc += tm[d] * w[(size_t)d * HH];
    g_ctxh[b * HH + h] = acc;
}

// ---------- Kernel 2: fused SGEMM (visual half) + ReLU + layer2 + sigmoid ----------
// Block: 64 rows x 256 cols, K tiled by 16. 256 threads (8 warps).
// Warp w owns rows w*8..w*8+7; lane owns cols lane*8..lane*8+7 (as 4 f32x2 pairs).
__global__ __launch_bounds__(256, 2) void scorer_kernel(
    const float* __restrict__ dv, const float* __restrict__ W1,
    const float* __restrict__ W2, const float* __restrict__ b2p)
{
    __shared__ __align__(16) float As[64][16];
    __shared__ __align__(16) float Bs[16][HH];

    int tid  = threadIdx.x;
    int warp = tid >> 5, lane = tid & 31;
    int row0 = blockIdx.x * 64;

    unsigned long long acc2[8][4];
    #pragma unroll
    for (int i = 0; i < 8; ++i)
        #pragma unroll
        for (int p = 0; p < 4; ++p) acc2[i][p] = 0ull;

    // global-load index mapping
    int ar = tid >> 2;                 // 0..63 (row in tile)
    int ac = (tid & 3) << 2;           // 0,4,8,12 (k within tile)
    const float* aG = dv + (size_t)(row0 + ar) * DD + ac;

    float4 aReg;
    float4 bReg[4];

    // prefetch tile 0
    aReg = *(const float4*)(aG);
    #pragma unroll
    for (int j = 0; j < 4; ++j) {
        int idx = tid + j * 256;               // 0..1023
        int kr = idx >> 6, c4 = (idx & 63) << 2;
        bReg[j] = *(const float4*)(W1 + (size_t)kr * HH + c4);
    }

    for (int k0 = 0; k0 < DD; k0 += 16) {
        if (k0) __syncthreads();               // previous compute done reading smem
        *(float4*)&As[ar][ac] = aReg;
        #pragma unroll
        for (int j = 0; j < 4; ++j) {
            int idx = tid + j * 256;
            int kr = idx >> 6, c4 = (idx & 63) << 2;
            *(float4*)&Bs[kr][c4] = bReg[j];
        }
        __syncthreads();

        if (k0 + 16 < DD) {                    // prefetch next tile into regs
            aReg = *(const float4*)(aG + k0 + 16);
            #pragma unroll
            for (int j = 0; j < 4; ++j) {
                int idx = tid + j * 256;
                int kr = idx >> 6, c4 = (idx & 63) << 2;
                bReg[j] = *(const float4*)(W1 + (size_t)(k0 + 16 + kr) * HH + c4);
            }
        }

        #pragma unroll
        for (int kk = 0; kk < 16; ++kk) {
            const ulonglong2* bp = (const ulonglong2*)&Bs[kk][lane << 3];
            ulonglong2 bv0 = bp[0], bv1 = bp[1];
            unsigned long long a2[8];
            #pragma unroll
            for (int i = 0; i < 8; ++i) a2[i] = pack2(As[(warp << 3) + i][kk]);
            #pragma unroll
            for (int i = 0; i < 8; ++i) {
                fma2(acc2[i][0], a2[i], bv0.x);
                fma2(acc2[i][1], a2[i], bv0.y);
                fma2(acc2[i][2], a2[i], bv1.x);
                fma2(acc2[i][3], a2[i], bv1.y);
            }
        }
    }

    // ---- fused epilogue: +ctx, ReLU, dot W2, sigmoid ----
    int b = blockIdx.x >> 4;           // 16 blocks (64 rows each) per batch of 1024
    float cc[8], ww[8];
    #pragma unroll
    for (int j = 0; j < 8; ++j) {
        cc[j] = g_ctxh[b * HH + (lane << 3) + j];
        ww[j] = W2[(lane << 3) + j];
    }
    float bias2 = b2p[0];
    #pragma unroll
    for (int i = 0; i < 8; ++i) {
        float lg = 0.f;
        #pragma unroll
        for (int p = 0; p < 4; ++p) {
            float2 v = unpack2(acc2[i][p]);
            float h0 = fmaxf(v.x + cc[2 * p], 0.f);
            float h1 = fmaxf(v.y + cc[2 * p + 1], 0.f);
            lg += h0 * ww[2 * p] + h1 * ww[2 * p + 1];
        }
        #pragma unroll
        for (int off = 16; off; off >>= 1)
            lg += __shfl_xor_sync(0xffffffffu, lg, off);
        if (lane == 0)
            g_scores[row0 + (warp << 3) + i] = 1.f / (1.f + expf(-(lg + bias2)));
    }
}

// ---------- Kernel 3: exact per-batch top-96 by rank counting ----------
// rank(i) = #{j : s_j > s_i  or (s_j == s_i and j < i)}  -> matches lax.top_k
// stable tie-break. Selected set = rank < 96; output position = prefix count
// of selected indices < i, which directly yields index-sorted top_k_idx.
__global__ __launch_bounds__(1024) void topk_kernel(float* outIdxF, int writeIdx)
{
    __shared__ float s[NN];
    __shared__ int flag[NN];
    int b = blockIdx.x, i = threadIdx.x;
    float si = g_scores[b * NN + i];
    s[i] = si;
    __syncthreads();
    int rank = 0;
    #pragma unroll 4
    for (int j = 0; j < NN; ++j) {
        float sj = s[j];
        rank += (sj > si) || (sj == si && j < i);
    }
    int f = (rank < KEEP) ? 1 : 0;
    flag[i] = f;
    __syncthreads();
    if (f) {
        int pos = 0;
        for (int j = 0; j < i; ++j) pos += flag[j];
        g_topk[b * KEEP + pos] = i;
        if (writeIdx) outIdxF[b * KEEP + pos] = (float)i;
    }
}

// ---------- Kernel 4: gather selected rows + register token ----------
__global__ __launch_bounds__(192) void gather_kernel(
    const float* __restrict__ dv, const float* __restrict__ regTok,
    float* __restrict__ out)
{
    int row = blockIdx.x;                    // 0 .. B*(KEEP+1)-1
    int b = row / (KEEP + 1), k = row % (KEEP + 1);
    const float* src = (k < KEEP)
        ? dv + ((size_t)b * NN + g_topk[b * KEEP + k]) * DD
        : regTok;
    float4 v = ((const float4*)src)[threadIdx.x];
    ((float4*)(out + (size_t)row * DD))[threadIdx.x] = v;
}

extern "C" void kernel_launch(void* const* d_in, const int* in_sizes, int n_in,
                              void* d_out, int out_size)
{
    const float* dv   = (const float*)d_in[0];   // [64,1024,768]
    const float* text = (const float*)d_in[1];   // [64,64,768]
    const float* W1   = (const float*)d_in[2];   // [1536,256]
    const float* b1   = (const float*)d_in[3];   // [256]
    const float* W2   = (const float*)d_in[4];   // [256,1]
    const float* b2   = (const float*)d_in[5];   // [1]
    const float* regT = (const float*)d_in[6];   // [1,1,768]
    float* out = (float*)d_out;

    (void)in_sizes; (void)n_in;

    ctx_kernel<<<BB, 256>>>(text, W1, b1);
    scorer_kernel<<<MM / 64, 256>>>(dv, W1, W2, b2);

    const int visElems = BB * (KEEP + 1) * DD;           // 4,773,888
    int writeIdx = (out_size >= visElems + BB * KEEP) ? 1 : 0;
    topk_kernel<<<BB, 1024>>>(out + visElems, writeIdx);
    gather_kernel<<<BB * (KEEP + 1), 192>>>(dv, regT, out);
}

// round 3
// speedup vs baseline: 1.3384x; 1.3384x over previous
#include <cuda_runtime.h>
#include <cuda_bf16.h>
#include <math.h>
#include <stdint.h>

#define BB 64
#define NN 1024
#define SS 64
#define DD 768
#define HH 256
#define KEEP 96
#define MM (BB*NN)

// ---------------- device scratch (no allocations allowed) ----------------
__device__ float          g_ctxh[BB*HH];
__device__ float          g_scores[MM];
__device__ int            g_topk[BB*KEEP];
__device__ __nv_bfloat16  g_Bhi[HH*DD];   // W1 visual half, transposed [h][d], bf16 hi
__device__ __nv_bfloat16  g_Blo[HH*DD];   // bf16 lo (residual)

// ---------------- smem layout (dynamic, bytes) ----------------
// A tiles: [buf][term][64 rows][40 halves]  (80B pitch, 64B used)
#define A_OFF(buf, term) ((uint32_t)(((buf)*2 + (term)) * 5120))
// B tiles: [buf][term][256 rows][40 halves]
#define B_OFF(buf, term) ((uint32_t)(20480 + ((buf)*2 + (term)) * 20480))
#define CTX_OFF  102400u
#define W2_OFF   103424u
#define PART_OFF 104448u
#define SMEM_BYTES 105472u

// ---------------- PTX helpers ----------------
__device__ __forceinline__ uint32_t smem_u32(const void* p) {
    uint32_t a;
    asm("{ .reg .u64 t; cvta.to.shared.u64 t, %1; cvt.u32.u64 %0, t; }" : "=r"(a) : "l"(p));
    return a;
}
__device__ __forceinline__ void ldsm4(uint32_t* r, uint32_t addr) {
    asm volatile("ldmatrix.sync.aligned.m8n8.x4.shared.b16 {%0,%1,%2,%3}, [%4];"
                 : "=r"(r[0]), "=r"(r[1]), "=r"(r[2]), "=r"(r[3]) : "r"(addr));
}
__device__ __forceinline__ void mma_bf16(float* d, const uint32_t* a, const uint32_t* b) {
    asm volatile(
        "mma.sync.aligned.m16n8k16.row.col.f32.bf16.bf16.f32 "
        "{%0,%1,%2,%3}, {%4,%5,%6,%7}, {%8,%9}, {%0,%1,%2,%3};"
        : "+f"(d[0]), "+f"(d[1]), "+f"(d[2]), "+f"(d[3])
        : "r"(a[0]), "r"(a[1]), "r"(a[2]), "r"(a[3]), "r"(b[0]), "r"(b[1]));
}
__device__ __forceinline__ void cpasync16(uint32_t dst, const void* src) {
    asm volatile("cp.async.ca.shared.global [%0], [%1], 16;" :: "r"(dst), "l"(src));
}
__device__ __forceinline__ void cpasync_commit() { asm volatile("cp.async.commit_group;"); }
__device__ __forceinline__ void cpasync_wait0()  { asm volatile("cp.async.wait_group 0;"); }

__device__ __forceinline__ void split_bf16(float x, uint32_t& hi_us, uint32_t& lo_us) {
    __nv_bfloat16 h = __float2bfloat16_rn(x);
    float r = x - __bfloat162float(h);
    __nv_bfloat16 l = __float2bfloat16_rn(r);
    hi_us = (uint32_t)__bfloat16_as_ushort(h);
    lo_us = (uint32_t)__bfloat16_as_ushort(l);
}

// ---------------- Kernel 0: split + transpose W1 visual half ----------------
__global__ __launch_bounds__(256) void prep_w1(const float* __restrict__ W1) {
    int e = blockIdx.x * 256 + threadIdx.x;     // 0 .. DD*HH-1
    int d = e >> 8, h = e & 255;
    float x = W1[(size_t)d * HH + h];
    uint32_t hi, lo; split_bf16(x, hi, lo);
    g_Bhi[h * DD + d] = __ushort_as_bfloat16((unsigned short)hi);
    g_Blo[h * DD + d] = __ushort_as_bfloat16((unsigned short)lo);
}

// ---------------- Kernel 1: text mean-pool + text half of layer 1 (fp32) ----------------
__global__ __launch_bounds__(256) void ctx_kernel(
    const float* __restrict__ text, const float* __restrict__ W1,
    const float* __restrict__ b1)
{
    __shared__ float tm[DD];
    int b = blockIdx.x, tid = threadIdx.x;
    for (int d = tid; d < DD; d += 256) {
        const float* p = text + (size_t)b * SS * DD + d;
        float s = 0.f;
        #pragma unroll 8
        for (int j = 0; j < SS; ++j) s += p[(size_t)j * DD];
        tm[d] = s * (1.0f / SS);
    }
    __syncthreads();
    int h = tid;
    float acc = b1[h];
    const float* w = W1 + (size_t)DD * HH + h;
    #pragma unroll 8
    for (int d = 0; d < DD; ++d) acc += tm[d] * w[(size_t)d * HH];
    g_ctxh[b * HH + h] = acc;
}

// ---------------- Kernel 2: bf16x3 HMMA GEMM + fused epilogue ----------------
// Block: M=64 x N=256, K-chunks of 32. 8 warps: warpM = wid>>2 (2), warpN = wid&3 (4).
// Warp tile 32x64. score = sigmoid( relu(D + ctx) . W2 + b2 ).
__global__ __launch_bounds__(256, 2) void scorer_mma(
    const float* __restrict__ dv, const float* __restrict__ W2,
    const float* __restrict__ b2p)
{
    extern __shared__ char smem[];
    uint32_t sb = smem_u32(smem);
    const int tid = threadIdx.x, wid = tid >> 5, lane = tid & 31;
    const int warpM = wid >> 2, warpN = wid & 3;
    const int row0 = blockIdx.x * 64;
    const int b = blockIdx.x >> 4;              // 16 blocks per batch

    ((float*)(smem + CTX_OFF))[tid] = g_ctxh[b * HH + tid];
    ((float*)(smem + W2_OFF))[tid]  = W2[tid];

    float acc[2][8][4];
    #pragma unroll
    for (int mt = 0; mt < 2; ++mt)
        #pragma unroll
        for (int j = 0; j < 8; ++j)
            #pragma unroll
            for (int r = 0; r < 4; ++r) acc[mt][j][r] = 0.f;

    // lane-invariant pieces of ldmatrix addresses
    const uint32_t a_row_l = (uint32_t)(lane & 15);
    const uint32_t a_k_l   = (uint32_t)((lane >> 4) << 3) * 2;   // byte offset
    const uint32_t b_n_l   = (uint32_t)((lane & 7) + ((lane >> 4) << 3));
    const uint32_t b_k_l   = (uint32_t)(((lane >> 3) & 1) << 3) * 2;

    // ---- chunk 0 load ----
    {
        // A: 64x32 fp32 -> split -> smem buf0
        #pragma unroll
        for (int i = 0; i < 2; ++i) {
            int idx = i * 256 + tid;
            int r = idx >> 3, q = idx & 7;
            float4 v = *(const float4*)(dv + (size_t)(row0 + r) * DD + q * 4);
            uint32_t h0,h1,h2,h3,l0,l1,l2,l3;
            split_bf16(v.x,h0,l0); split_bf16(v.y,h1,l1);
            split_bf16(v.z,h2,l2); split_bf16(v.w,h3,l3);
            uint2 hv = { h0 | (h1<<16), h2 | (h3<<16) };
            uint2 lv = { l0 | (l1<<16), l2 | (l3<<16) };
            *(uint2*)(smem + A_OFF(0,0) + r*80 + q*8) = hv;
            *(uint2*)(smem + A_OFF(0,1) + r*80 + q*8) = lv;
        }
        // B via cp.async
        #pragma unroll
        for (int i = 0; i < 8; ++i) {
            int idx = i * 256 + tid;
            int kq = idx & 3, n = (idx >> 2) & 255, term = idx >> 10;
            const __nv_bfloat16* src = (term ? g_Blo : g_Bhi) + (size_t)n * DD + kq * 8;
            cpasync16(sb + B_OFF(0, term) + n*80 + kq*16, src);
        }
        cpasync_commit();
        cpasync_wait0();
    }
    __syncthreads();

    for (int c = 0; c < 24; ++c) {
        const int cur = c & 1, nxt = cur ^ 1;
        float4 aReg[2];

        if (c < 23) {
            const int k0 = (c + 1) * 32;
            #pragma unroll
            for (int i = 0; i < 8; ++i) {
                int idx = i * 256 + tid;
                int kq = idx & 3, n = (idx >> 2) & 255, term = idx >> 10;
                const __nv_bfloat16* src = (term ? g_Blo : g_Bhi) + (size_t)n * DD + k0 + kq * 8;
                cpasync16(sb + B_OFF(nxt, term) + n*80 + kq*16, src);
            }
            cpasync_commit();
            #pragma unroll
            for (int i = 0; i < 2; ++i) {
                int idx = i * 256 + tid;
                int r = idx >> 3, q = idx & 7;
                aReg[i] = *(const float4*)(dv + (size_t)(row0 + r) * DD + k0 + q * 4);
            }
        }

        // ---- compute on cur ----
        const uint32_t Ah = sb + A_OFF(cur,0), Al = sb + A_OFF(cur,1);
        const uint32_t Bh = sb + B_OFF(cur,0), Bl = sb + B_OFF(cur,1);
        #pragma unroll
        for (int kk = 0; kk < 2; ++kk) {
            const uint32_t kbyte = (uint32_t)(kk * 32);    // kk*16 halves
            uint32_t ah[2][4], al[2][4];
            #pragma unroll
            for (int mt = 0; mt < 2; ++mt) {
                uint32_t aoff = (uint32_t)(warpM*32 + mt*16 + a_row_l)*80 + kbyte + a_k_l;
                ldsm4(ah[mt], Ah + aoff);
                ldsm4(al[mt], Al + aoff);
            }
            #pragma unroll
            for (int g = 0; g < 2; ++g) {
                uint32_t bh[4][2], bl[4][2];
                #pragma unroll
                for (int pp = 0; pp < 2; ++pp) {
                    uint32_t boff = (uint32_t)(warpN*64 + g*32 + pp*16 + b_n_l)*80 + kbyte + b_k_l;
                    ldsm4(&bh[pp*2][0], Bh + boff);
                    ldsm4(&bl[pp*2][0], Bl + boff);
                }
                #pragma unroll
                for (int mt = 0; mt < 2; ++mt)
                    #pragma unroll
                    for (int j = 0; j < 4; ++j) {
                        float* d = acc[mt][g*4 + j];
                        mma_bf16(d, ah[mt], bh[j]);
                        mma_bf16(d, ah[mt], bl[j]);
                        mma_bf16(d, al[mt], bh[j]);
                    }
            }
        }

        if (c < 23) {
            #pragma unroll
            for (int i = 0; i < 2; ++i) {
                int idx = i * 256 + tid;
                int r = idx >> 3, q = idx & 7;
                float4 v = aReg[i];
                uint32_t h0,h1,h2,h3,l0,l1,l2,l3;
                split_bf16(v.x,h0,l0); split_bf16(v.y,h1,l1);
                split_bf16(v.z,h2,l2); split_bf16(v.w,h3,l3);
                uint2 hv = { h0 | (h1<<16), h2 | (h3<<16) };
                uint2 lv = { l0 | (l1<<16), l2 | (l3<<16) };
                *(uint2*)(smem + A_OFF(nxt,0) + r*80 + q*8) = hv;
                *(uint2*)(smem + A_OFF(nxt,1) + r*80 + q*8) = lv;
            }
            cpasync_wait0();
        }
        __syncthreads();
    }

    // ---- fused epilogue ----
    const float* sctx = (const float*)(smem + CTX_OFF);
    const float* sw2  = (const float*)(smem + W2_OFF);
    float lg[4] = {0.f, 0.f, 0.f, 0.f};      // rows: mt*16 + {lane/4, lane/4+8}
    #pragma unroll
    for (int mt = 0; mt < 2; ++mt)
        #pragma unroll
        for (int j = 0; j < 8; ++j) {
            int n = warpN*64 + j*8 + (lane & 3)*2;
            float c0 = sctx[n], c1 = sctx[n+1], w0 = sw2[n], w1 = sw2[n+1];
            lg[mt*2+0] += fmaxf(acc[mt][j][0] + c0, 0.f) * w0
                        + fmaxf(acc[mt][j][1] + c1, 0.f) * w1;
            lg[mt*2+1] += fmaxf(acc[mt][j][2] + c0, 0.f) * w0
                        + fmaxf(acc[mt][j][3] + c1, 0.f) * w1;
        }
    #pragma unroll
    for (int i = 0; i < 4; ++i) {
        lg[i] += __shfl_xor_sync(0xffffffffu, lg[i], 1);
        lg[i] += __shfl_xor_sync(0xffffffffu, lg[i], 2);
    }
    float* part = (float*)(smem + PART_OFF);   // [64][4]
    if ((lane & 3) == 0) {
        #pragma unroll
        for (int i = 0; i < 4; ++i) {
            int row = warpM*32 + (i >> 1)*16 + (i & 1)*8 + (lane >> 2);
            part[row * 4 + warpN] = lg[i];
        }
    }
    __syncthreads();
    if (tid < 64) {
        float s = part[tid*4+0] + part[tid*4+1] + part[tid*4+2] + part[tid*4+3] + b2p[0];
        g_scores[row0 + tid] = 1.f / (1.f + expf(-s));
    }
}

// ---------------- Kernel 3: exact per-batch top-96 (rank counting) ----------------
__global__ __launch_bounds__(1024) void topk_kernel(float* outIdxF, int writeIdx)
{
    __shared__ float s[NN];
    __shared__ int flag[NN];
    int b = blockIdx.x, i = threadIdx.x;
    float si = g_scores[b * NN + i];
    s[i] = si;
    __syncthreads();
    int rank = 0;
    #pragma unroll 4
    for (int j = 0; j < NN; ++j) {
        float sj = s[j];
        rank += (sj > si) || (sj == si && j < i);
    }
    int f = (rank < KEEP) ? 1 : 0;
    flag[i] = f;
    __syncthreads();
    if (f) {
        int pos = 0;
        for (int j = 0; j < i; ++j) pos += flag[j];
        g_topk[b * KEEP + pos] = i;
        if (writeIdx) outIdxF[b * KEEP + pos] = (float)i;
    }
}

// ---------------- Kernel 4: gather selected rows + register token ----------------
__global__ __launch_bounds__(192) void gather_kernel(
    const float* __restrict__ dv, const float* __restrict__ regTok,
    float* __restrict__ out)
{
    int row = blockIdx.x;
    int b = row / (KEEP + 1), k = row % (KEEP + 1);
    const float* src = (k < KEEP)
        ? dv + ((size_t)b * NN + g_topk[b * KEEP + k]) * DD
        : regTok;
    float4 v = ((const float4*)src)[threadIdx.x];
    ((float4*)(out + (size_t)row * DD))[threadIdx.x] = v;
}

extern "C" void kernel_launch(void* const* d_in, const int* in_sizes, int n_in,
                              void* d_out, int out_size)
{
    const float* dv   = (const float*)d_in[0];
    const float* text = (const float*)d_in[1];
    const float* W1   = (const float*)d_in[2];
    const float* b1   = (const float*)d_in[3];
    const float* W2   = (const float*)d_in[4];
    const float* b2   = (const float*)d_in[5];
    const float* regT = (const float*)d_in[6];
    float* out = (float*)d_out;
    (void)in_sizes; (void)n_in;

    static int smem_set = 0;
    if (!smem_set) {
        cudaFuncSetAttribute(scorer_mma, cudaFuncAttributeMaxDynamicSharedMemorySize, SMEM_BYTES);
        smem_set = 1;
    }

    prep_w1<<<DD * HH / 256, 256>>>(W1);
    ctx_kernel<<<BB, 256>>>(text, W1, b1);
    scorer_mma<<<MM / 64, 256, SMEM_BYTES>>>(dv, W2, b2);

    const int visElems = BB * (KEEP + 1) * DD;
    int writeIdx = (out_size >= visElems + BB * KEEP) ? 1 : 0;
    topk_kernel<<<BB, 1024>>>(out + visElems, writeIdx);
    gather_kernel<<<BB * (KEEP + 1), 192>>>(dv, regT, out);
}

// round 4
// speedup vs baseline: 2.0679x; 1.5451x over previous
#include <cuda_runtime.h>
#include <cuda_bf16.h>
#include <math.h>
#include <stdint.h>

#define BB 64
#define NN 1024
#define SS 64
#define DD 768
#define HH 256
#define KEEP 96
#define MM (BB*NN)

// ---------------- device scratch (no allocations allowed) ----------------
__device__ float          g_ctxh[BB*HH];
__device__ float          g_scores[MM];
__device__ int            g_topk[BB*KEEP];
__device__ __nv_bfloat16  g_Bhi[HH*DD];   // W1 visual half, transposed [h][d], bf16 hi
__device__ __nv_bfloat16  g_Blo[HH*DD];   // bf16 lo (residual)

// ---------------- smem layout (dynamic, bytes), 80B pitch tiles ----------------
// A: [buf][term][64 rows][40 halves]   (5120 B each)
#define A_OFF(buf, term) ((uint32_t)(((buf)*2 + (term)) * 5120))
// B: [buf][term][256 rows][40 halves]  (20480 B each)
#define B_OFF(buf, term) ((uint32_t)(20480 + ((buf)*2 + (term)) * 20480))
#define CTX_OFF  102400u
#define W2_OFF   103424u
#define PART_OFF 104448u
#define SMEM_BYTES 105472u

// ---------------- PTX helpers ----------------
__device__ __forceinline__ uint32_t smem_u32(const void* p) {
    uint32_t a;
    asm("{ .reg .u64 t; cvta.to.shared.u64 t, %1; cvt.u32.u64 %0, t; }" : "=r"(a) : "l"(p));
    return a;
}
__device__ __forceinline__ void ldsm4(uint32_t* r, uint32_t addr) {
    asm volatile("ldmatrix.sync.aligned.m8n8.x4.shared.b16 {%0,%1,%2,%3}, [%4];"
                 : "=r"(r[0]), "=r"(r[1]), "=r"(r[2]), "=r"(r[3]) : "r"(addr));
}
__device__ __forceinline__ void mma_bf16(float* d, const uint32_t* a, const uint32_t* b) {
    asm volatile(
        "mma.sync.aligned.m16n8k16.row.col.f32.bf16.bf16.f32 "
        "{%0,%1,%2,%3}, {%4,%5,%6,%7}, {%8,%9}, {%0,%1,%2,%3};"
        : "+f"(d[0]), "+f"(d[1]), "+f"(d[2]), "+f"(d[3])
        : "r"(a[0]), "r"(a[1]), "r"(a[2]), "r"(a[3]), "r"(b[0]), "r"(b[1]));
}
__device__ __forceinline__ void cpasync16(uint32_t dst, const void* src) {
    asm volatile("cp.async.ca.shared.global [%0], [%1], 16;" :: "r"(dst), "l"(src));
}
__device__ __forceinline__ void cpasync_commit() { asm volatile("cp.async.commit_group;"); }
__device__ __forceinline__ void cpasync_wait0()  { asm volatile("cp.async.wait_group 0;"); }

__device__ __forceinline__ void split_bf16(float x, uint32_t& hi_us, uint32_t& lo_us) {
    __nv_bfloat16 h = __float2bfloat16_rn(x);
    float r = x - __bfloat162float(h);
    __nv_bfloat16 l = __float2bfloat16_rn(r);
    hi_us = (uint32_t)__bfloat16_as_ushort(h);
    lo_us = (uint32_t)__bfloat16_as_ushort(l);
}

// ---------------- Kernel 0: split + transpose W1 visual half ----------------
__global__ __launch_bounds__(256) void prep_w1(const float* __restrict__ W1) {
    int e = blockIdx.x * 256 + threadIdx.x;     // 0 .. DD*HH-1
    int d = e >> 8, h = e & 255;
    float x = W1[(size_t)d * HH + h];
    uint32_t hi, lo; split_bf16(x, hi, lo);
    g_Bhi[h * DD + d] = __ushort_as_bfloat16((unsigned short)hi);
    g_Blo[h * DD + d] = __ushort_as_bfloat16((unsigned short)lo);
}

// ---------------- Kernel 1: text mean-pool + text half of layer 1 (fp32) ----------------
__global__ __launch_bounds__(256) void ctx_kernel(
    const float* __restrict__ text, const float* __restrict__ W1,
    const float* __restrict__ b1)
{
    __shared__ float tm[DD];
    int b = blockIdx.x, tid = threadIdx.x;
    for (int d = tid; d < DD; d += 256) {
        const float* p = text + (size_t)b * SS * DD + d;
        float s = 0.f;
        #pragma unroll 8
        for (int j = 0; j < SS; ++j) s += p[(size_t)j * DD];
        tm[d] = s * (1.0f / SS);
    }
    __syncthreads();
    int h = tid;
    float acc = b1[h];
    const float* w = W1 + (size_t)DD * HH + h;
    #pragma unroll 8
    for (int d = 0; d < DD; ++d) acc += tm[d] * w[(size_t)d * HH];
    g_ctxh[b * HH + h] = acc;
}

// ---------------- Kernel 2: bf16x3 HMMA GEMM + fused epilogue ----------------
// Block: 512 threads (16 warps), tile M=64 x N=256, K-chunks of 32.
// Warp grid 4(M) x 4(N); warp tile 16x64 -> 32 acc regs/thread (no spills, occ 2).
__global__ __launch_bounds__(512, 2) void scorer_mma(
    const float* __restrict__ dv, const float* __restrict__ W2,
    const float* __restrict__ b2p)
{
    extern __shared__ char smem[];
    uint32_t sb = smem_u32(smem);
    const int tid = threadIdx.x, wid = tid >> 5, lane = tid & 31;
    const int warpM = wid >> 2, warpN = wid & 3;
    const int row0 = blockIdx.x * 64;
    const int b = blockIdx.x >> 4;              // 16 blocks per batch

    if (tid < 256) {
        ((float*)(smem + CTX_OFF))[tid] = g_ctxh[b * HH + tid];
        ((float*)(smem + W2_OFF))[tid]  = W2[tid];
    }

    float acc[8][4];
    #pragma unroll
    for (int j = 0; j < 8; ++j)
        #pragma unroll
        for (int r = 0; r < 4; ++r) acc[j][r] = 0.f;

    // lane-invariant ldmatrix address pieces
    const uint32_t a_row_l = (uint32_t)(lane & 15);
    const uint32_t a_k_l   = (uint32_t)(lane >> 4) * 16u;      // bytes
    const uint32_t b_n_l   = (uint32_t)((lane & 7) + ((lane >> 4) << 3));
    const uint32_t b_k_l   = (uint32_t)((lane >> 3) & 1) * 16u;

    // A global mapping: one float4 per thread per chunk
    const int ar = tid >> 3, aq = tid & 7;
    const float* aG = dv + (size_t)(row0 + ar) * DD + aq * 4;
    const uint32_t aStOff = (uint32_t)(ar * 80 + aq * 8);

    // ---- chunk 0 ----
    {
        float4 v = *(const float4*)aG;
        uint32_t h0,h1,h2,h3,l0,l1,l2,l3;
        split_bf16(v.x,h0,l0); split_bf16(v.y,h1,l1);
        split_bf16(v.z,h2,l2); split_bf16(v.w,h3,l3);
        uint2 hv = { h0 | (h1<<16), h2 | (h3<<16) };
        uint2 lv = { l0 | (l1<<16), l2 | (l3<<16) };
        *(uint2*)(smem + A_OFF(0,0) + aStOff) = hv;
        *(uint2*)(smem + A_OFF(0,1) + aStOff) = lv;
        #pragma unroll
        for (int i = 0; i < 4; ++i) {
            int idx = i * 512 + tid;
            int kq = idx & 3, n = (idx >> 2) & 255, term = idx >> 10;
            const __nv_bfloat16* src = (term ? g_Blo : g_Bhi) + (size_t)n * DD + kq * 8;
            cpasync16(sb + B_OFF(0, term) + n*80 + kq*16, src);
        }
        cpasync_commit();
        cpasync_wait0();
    }
    __syncthreads();

    for (int c = 0; c < 24; ++c) {
        const int cur = c & 1, nxt = cur ^ 1;
        float4 aReg;

        if (c < 23) {
            const int k0 = (c + 1) * 32;
            #pragma unroll
            for (int i = 0; i < 4; ++i) {
                int idx = i * 512 + tid;
                int kq = idx & 3, n = (idx >> 2) & 255, term = idx >> 10;
                const __nv_bfloat16* src = (term ? g_Blo : g_Bhi) + (size_t)n * DD + k0 + kq * 8;
                cpasync16(sb + B_OFF(nxt, term) + n*80 + kq*16, src);
            }
            cpasync_commit();
            aReg = *(const float4*)(aG + k0);
        }

        // ---- compute on cur ----
        const uint32_t Ah = sb + A_OFF(cur,0), Al = sb + A_OFF(cur,1);
        const uint32_t Bh = sb + B_OFF(cur,0), Bl = sb + B_OFF(cur,1);
        #pragma unroll
        for (int kk = 0; kk < 2; ++kk) {
            const uint32_t kb = (uint32_t)(kk * 32);
            uint32_t ah[4], al[4];
            const uint32_t aoff = (uint32_t)(warpM*16 + a_row_l)*80 + kb + a_k_l;
            ldsm4(ah, Ah + aoff);
            ldsm4(al, Al + aoff);
            #pragma unroll
            for (int nt = 0; nt < 4; ++nt) {
                uint32_t bh[4], bl[4];
                const uint32_t boff = (uint32_t)(warpN*64 + nt*16 + b_n_l)*80 + kb + b_k_l;
                ldsm4(bh, Bh + boff);
                ldsm4(bl, Bl + boff);
                float* d0 = acc[nt*2], *d1 = acc[nt*2+1];
                mma_bf16(d0, ah, bh);     mma_bf16(d1, ah, bh+2);
                mma_bf16(d0, ah, bl);     mma_bf16(d1, ah, bl+2);
                mma_bf16(d0, al, bh);     mma_bf16(d1, al, bh+2);
            }
        }

        if (c < 23) {
            uint32_t h0,h1,h2,h3,l0,l1,l2,l3;
            split_bf16(aReg.x,h0,l0); split_bf16(aReg.y,h1,l1);
            split_bf16(aReg.z,h2,l2); split_bf16(aReg.w,h3,l3);
            uint2 hv = { h0 | (h1<<16), h2 | (h3<<16) };
            uint2 lv = { l0 | (l1<<16), l2 | (l3<<16) };
            *(uint2*)(smem + A_OFF(nxt,0) + aStOff) = hv;
            *(uint2*)(smem + A_OFF(nxt,1) + aStOff) = lv;
            cpasync_wait0();
        }
        __syncthreads();
    }

    // ---- fused epilogue: +ctx, ReLU, dot W2, sigmoid ----
    const float* sctx = (const float*)(smem + CTX_OFF);
    const float* sw2  = (const float*)(smem + W2_OFF);
    float lg0 = 0.f, lg1 = 0.f;       // rows warpM*16 + lane/4, +8
    #pragma unroll
    for (int j = 0; j < 8; ++j) {
        int n = warpN*64 + j*8 + (lane & 3)*2;
        float c0 = sctx[n], c1 = sctx[n+1], w0 = sw2[n], w1 = sw2[n+1];
        lg0 += fmaxf(acc[j][0] + c0, 0.f) * w0 + fmaxf(acc[j][1] + c1, 0.f) * w1;
        lg1 += fmaxf(acc[j][2] + c0, 0.f) * w0 + fmaxf(acc[j][3] + c1, 0.f) * w1;
    }
    lg0 += __shfl_xor_sync(0xffffffffu, lg0, 1);
    lg0 += __shfl_xor_sync(0xffffffffu, lg0, 2);
    lg1 += __shfl_xor_sync(0xffffffffu, lg1, 1);
    lg1 += __shfl_xor_sync(0xffffffffu, lg1, 2);
    float* part = (float*)(smem + PART_OFF);   // [64][4]
    if ((lane & 3) == 0) {
        int r0 = warpM*16 + (lane >> 2);
        part[r0 * 4 + warpN]       = lg0;
        part[(r0 + 8) * 4 + warpN] = lg1;
    }
    __syncthreads();
    if (tid < 64) {
        float s = part[tid*4+0] + part[tid*4+1] + part[tid*4+2] + part[tid*4+3] + b2p[0];
        g_scores[row0 + tid] = 1.f / (1.f + expf(-s));
    }
}

// ---------------- Kernel 3: top-96 via 32-step syncthreads_count binary search ----------------
// Scores are sigmoid outputs (>0) -> float bits are order-isomorphic to values.
// Find exact 96th-largest bit pattern; ties broken by lowest index (lax.top_k stable).
__global__ __launch_bounds__(1024) void topk_kernel(float* outIdxF, int writeIdx)
{
    __shared__ int weq[32], wsel[32];
    int b = blockIdx.x, i = threadIdx.x;
    int lane = i & 31, warp = i >> 5;
    unsigned ui = __float_as_uint(g_scores[b * NN + i]);

    unsigned thr = 0;
    #pragma unroll
    for (int bit = 31; bit >= 0; --bit) {
        unsigned trial = thr | (1u << bit);
        int c = __syncthreads_count(ui >= trial);
        if (c >= KEEP) thr = trial;          // uniform across block
    }
    // thr == 96th largest value
    int isGT = ui > thr;
    int isEQ = (ui == thr);
    int cntGT = __syncthreads_count(isGT);
    int k2 = KEEP - cntGT;                   // slots for tied values, lowest index first

    unsigned lmlt = (lane == 0) ? 0u : (0xffffffffu >> (32 - lane));
    unsigned eqm = __ballot_sync(0xffffffffu, isEQ);
    if (lane == 0) weq[warp] = __popc(eqm);
    __syncthreads();
    int eqBefore = __popc(eqm & lmlt);
    #pragma unroll
    for (int w = 0; w < 32; ++w) if (w < warp) eqBefore += weq[w];

    int flag = isGT || (isEQ && eqBefore < k2);
    unsigned sm_ = __ballot_sync(0xffffffffu, flag);
    if (lane == 0) wsel[warp] = __popc(sm_);
    __syncthreads();
    int pos = __popc(sm_ & lmlt);
    #pragma unroll
    for (int w = 0; w < 32; ++w) if (w < warp) pos += wsel[w];

    if (flag) {
        g_topk[b * KEEP + pos] = i;
        if (writeIdx) outIdxF[b * KEEP + pos] = (float)i;
    }
}

// ---------------- Kernel 4: gather selected rows + register token ----------------
__global__ __launch_bounds__(192) void gather_kernel(
    const float* __restrict__ dv, const float* __restrict__ regTok,
    float* __restrict__ out)
{
    int row = blockIdx.x;
    int b = row / (KEEP + 1), k = row % (KEEP + 1);
    const float* src = (k < KEEP)
        ? dv + ((size_t)b * NN + g_topk[b * KEEP + k]) * DD
        : regTok;
    float4 v = ((const float4*)src)[threadIdx.x];
    ((float4*)(out + (size_t)row * DD))[threadIdx.x] = v;
}

extern "C" void kernel_launch(void* const* d_in, const int* in_sizes, int n_in,
                              void* d_out, int out_size)
{
    const float* dv   = (const float*)d_in[0];
    const float* text = (const float*)d_in[1];
    const float* W1   = (const float*)d_in[2];
    const float* b1   = (const float*)d_in[3];
    const float* W2   = (const float*)d_in[4];
    const float* b2   = (const float*)d_in[5];
    const float* regT = (const float*)d_in[6];
    float* out = (float*)d_out;
    (void)in_sizes; (void)n_in;

    static int smem_set = 0;
    if (!smem_set) {
        cudaFuncSetAttribute(scorer_mma, cudaFuncAttributeMaxDynamicSharedMemorySize, SMEM_BYTES);
        smem_set = 1;
    }

    prep_w1<<<DD * HH / 256, 256>>>(W1);
    ctx_kernel<<<BB, 256>>>(text, W1, b1);
    scorer_mma<<<MM / 64, 512, SMEM_BYTES>>>(dv, W2, b2);

    const int visElems = BB * (KEEP + 1) * DD;
    int writeIdx = (out_size >= visElems + BB * KEEP) ? 1 : 0;
    topk_kernel<<<BB, 1024>>>(out + visElems, writeIdx);
    gather_kernel<<<BB * (KEEP + 1), 192>>>(dv, regT, out);
}

// round 5
// speedup vs baseline: 2.7370x; 1.3236x over previous
#include <cuda_runtime.h>
#include <cuda_bf16.h>
#include <math.h>
#include <stdint.h>

#define BB 64
#define NN 1024
#define SS 64
#define DD 768
#define HH 256
#define KEEP 96
#define CAND 128
#define MM (BB*NN)
#define KSPLIT 3

// ---------------- device scratch (no allocations allowed) ----------------
__device__ float          g_ctxh[BB*HH];
__device__ float          g_scoresA[MM];          // approx logits
__device__ int            g_cand[BB*CAND];        // approx top-128, index-sorted
__device__ int            g_topk[BB*KEEP];
__device__ __nv_bfloat16  g_Bhi[HH*DD];           // W1 visual half, [h][d], bf16 hi
__device__ __nv_bfloat16  g_Blo[HH*DD];           // bf16 lo residual
__device__ float          g_part[KSPLIT*BB*CAND*HH];  // refine partials (25.2 MB)

// ---------------- PTX helpers ----------------
__device__ __forceinline__ uint32_t smem_u32(const void* p) {
    uint32_t a;
    asm("{ .reg .u64 t; cvta.to.shared.u64 t, %1; cvt.u32.u64 %0, t; }" : "=r"(a) : "l"(p));
    return a;
}
__device__ __forceinline__ void ldsm4(uint32_t* r, uint32_t addr) {
    asm volatile("ldmatrix.sync.aligned.m8n8.x4.shared.b16 {%0,%1,%2,%3}, [%4];"
                 : "=r"(r[0]), "=r"(r[1]), "=r"(r[2]), "=r"(r[3]) : "r"(addr));
}
__device__ __forceinline__ void mma_bf16(float* d, const uint32_t* a, const uint32_t* b) {
    asm volatile(
        "mma.sync.aligned.m16n8k16.row.col.f32.bf16.bf16.f32 "
        "{%0,%1,%2,%3}, {%4,%5,%6,%7}, {%8,%9}, {%0,%1,%2,%3};"
        : "+f"(d[0]), "+f"(d[1]), "+f"(d[2]), "+f"(d[3])
        : "r"(a[0]), "r"(a[1]), "r"(a[2]), "r"(a[3]), "r"(b[0]), "r"(b[1]));
}
__device__ __forceinline__ void cpasync16(uint32_t dst, const void* src) {
    asm volatile("cp.async.ca.shared.global [%0], [%1], 16;" :: "r"(dst), "l"(src));
}
__device__ __forceinline__ void cpasync_commit() { asm volatile("cp.async.commit_group;"); }
__device__ __forceinline__ void cpasync_wait0()  { asm volatile("cp.async.wait_group 0;"); }

__device__ __forceinline__ void split_bf16(float x, uint32_t& hi_us, uint32_t& lo_us) {
    __nv_bfloat16 h = __float2bfloat16_rn(x);
    float r = x - __bfloat162float(h);
    __nv_bfloat16 l = __float2bfloat16_rn(r);
    hi_us = (uint32_t)__bfloat16_as_ushort(h);
    lo_us = (uint32_t)__bfloat16_as_ushort(l);
}
__device__ __forceinline__ uint32_t bf16_hi(float x) {
    return (uint32_t)__bfloat16_as_ushort(__float2bfloat16_rn(x));
}

// ---------------- Kernel 0: split + transpose W1 visual half ----------------
__global__ __launch_bounds__(256) void prep_w1(const float* __restrict__ W1) {
    int e = blockIdx.x * 256 + threadIdx.x;
    int d = e >> 8, h = e & 255;
    float x = W1[(size_t)d * HH + h];
    uint32_t hi, lo; split_bf16(x, hi, lo);
    g_Bhi[h * DD + d] = __ushort_as_bfloat16((unsigned short)hi);
    g_Blo[h * DD + d] = __ushort_as_bfloat16((unsigned short)lo);
}

// ---------------- Kernel 1: text mean-pool + text half of layer 1 (fp32) ----------------
__global__ __launch_bounds__(256) void ctx_kernel(
    const float* __restrict__ text, const float* __restrict__ W1,
    const float* __restrict__ b1)
{
    __shared__ float tm[DD];
    int b = blockIdx.x, tid = threadIdx.x;
    for (int d = tid; d < DD; d += 256) {
        const float* p = text + (size_t)b * SS * DD + d;
        float s = 0.f;
        #pragma unroll 8
        for (int j = 0; j < SS; ++j) s += p[(size_t)j * DD];
        tm[d] = s * (1.0f / SS);
    }
    __syncthreads();
    int h = tid;
    float acc = b1[h];
    const float* w = W1 + (size_t)DD * HH + h;
    #pragma unroll 8
    for (int d = 0; d < DD; ++d) acc += tm[d] * w[(size_t)d * HH];
    g_ctxh[b * HH + h] = acc;
}

// ================= Approx scorer: 1-term bf16 HMMA + fused epilogue =================
// Block 512 thr (16 warps 4Mx4N), tile M=64 x N=256, K-chunks 32. Stores approx LOGIT.
#define SA_A(buf)  ((uint32_t)((buf)*5120))
#define SA_B(buf)  ((uint32_t)(10240 + (buf)*20480))
#define SA_CTX 51200u
#define SA_W2  52224u
#define SA_PART 53248u
#define SA_BYTES 54272u

__global__ __launch_bounds__(512, 2) void scorer_approx(
    const float* __restrict__ dv, const float* __restrict__ W2,
    const float* __restrict__ b2p)
{
    extern __shared__ char smem[];
    uint32_t sb = smem_u32(smem);
    const int tid = threadIdx.x, wid = tid >> 5, lane = tid & 31;
    const int warpM = wid >> 2, warpN = wid & 3;
    const int row0 = blockIdx.x * 64;
    const int b = blockIdx.x >> 4;

    if (tid < 256) {
        ((float*)(smem + SA_CTX))[tid] = g_ctxh[b * HH + tid];
        ((float*)(smem + SA_W2))[tid]  = W2[tid];
    }

    float acc[8][4];
    #pragma unroll
    for (int j = 0; j < 8; ++j)
        #pragma unroll
        for (int r = 0; r < 4; ++r) acc[j][r] = 0.f;

    const uint32_t a_row_l = (uint32_t)(lane & 15);
    const uint32_t a_k_l   = (uint32_t)(lane >> 4) * 16u;
    const uint32_t b_n_l   = (uint32_t)((lane & 7) + ((lane >> 4) << 3));
    const uint32_t b_k_l   = (uint32_t)((lane >> 3) & 1) * 16u;

    const int ar = tid >> 3, aq = tid & 7;
    const float* aG = dv + (size_t)(row0 + ar) * DD + aq * 4;
    const uint32_t aStOff = (uint32_t)(ar * 80 + aq * 8);

    { // chunk 0
        float4 v = *(const float4*)aG;
        uint2 hv = { bf16_hi(v.x) | (bf16_hi(v.y) << 16),
                     bf16_hi(v.z) | (bf16_hi(v.w) << 16) };
        *(uint2*)(smem + SA_A(0) + aStOff) = hv;
        #pragma unroll
        for (int i = 0; i < 2; ++i) {
            int idx = i * 512 + tid;
            int kq = idx & 3, n = idx >> 2;
            cpasync16(sb + SA_B(0) + n*80 + kq*16, g_Bhi + (size_t)n * DD + kq * 8);
        }
        cpasync_commit();
        cpasync_wait0();
    }
    __syncthreads();

    for (int c = 0; c < 24; ++c) {
        const int cur = c & 1, nxt = cur ^ 1;
        float4 aReg;
        if (c < 23) {
            const int k0 = (c + 1) * 32;
            #pragma unroll
            for (int i = 0; i < 2; ++i) {
                int idx = i * 512 + tid;
                int kq = idx & 3, n = idx >> 2;
                cpasync16(sb + SA_B(nxt) + n*80 + kq*16, g_Bhi + (size_t)n * DD + k0 + kq * 8);
            }
            cpasync_commit();
            aReg = *(const float4*)(aG + k0);
        }

        const uint32_t Ah = sb + SA_A(cur), Bh = sb + SA_B(cur);
        #pragma unroll
        for (int kk = 0; kk < 2; ++kk) {
            const uint32_t kb = (uint32_t)(kk * 32);
            uint32_t ah[4];
            ldsm4(ah, Ah + (uint32_t)(warpM*16 + a_row_l)*80 + kb + a_k_l);
            #pragma unroll
            for (int nt = 0; nt < 4; ++nt) {
                uint32_t bh[4];
                ldsm4(bh, Bh + (uint32_t)(warpN*64 + nt*16 + b_n_l)*80 + kb + b_k_l);
                mma_bf16(acc[nt*2],   ah, bh);
                mma_bf16(acc[nt*2+1], ah, bh+2);
            }
        }

        if (c < 23) {
            uint2 hv = { bf16_hi(aReg.x) | (bf16_hi(aReg.y) << 16),
                         bf16_hi(aReg.z) | (bf16_hi(aReg.w) << 16) };
            *(uint2*)(smem + SA_A(nxt) + aStOff) = hv;
            cpasync_wait0();
        }
        __syncthreads();
    }

    // epilogue: +ctx, relu, dot W2 -> approx logit
    const float* sctx = (const float*)(smem + SA_CTX);
    const float* sw2  = (const float*)(smem + SA_W2);
    float lg0 = 0.f, lg1 = 0.f;
    #pragma unroll
    for (int j = 0; j < 8; ++j) {
        int n = warpN*64 + j*8 + (lane & 3)*2;
        float c0 = sctx[n], c1 = sctx[n+1], w0 = sw2[n], w1 = sw2[n+1];
        lg0 += fmaxf(acc[j][0] + c0, 0.f) * w0 + fmaxf(acc[j][1] + c1, 0.f) * w1;
        lg1 += fmaxf(acc[j][2] + c0, 0.f) * w0 + fmaxf(acc[j][3] + c1, 0.f) * w1;
    }
    lg0 += __shfl_xor_sync(0xffffffffu, lg0, 1);
    lg0 += __shfl_xor_sync(0xffffffffu, lg0, 2);
    lg1 += __shfl_xor_sync(0xffffffffu, lg1, 1);
    lg1 += __shfl_xor_sync(0xffffffffu, lg1, 2);
    float* part = (float*)(smem + SA_PART);
    if ((lane & 3) == 0) {
        int r0 = warpM*16 + (lane >> 2);
        part[r0 * 4 + warpN]       = lg0;
        part[(r0 + 8) * 4 + warpN] = lg1;
    }
    __syncthreads();
    if (tid < 64)
        g_scoresA[row0 + tid] = part[tid*4] + part[tid*4+1] + part[tid*4+2] + part[tid*4+3] + b2p[0];
}

// ---------------- approx top-128 (binary search on signed-float order) ----------------
__global__ __launch_bounds__(1024) void topk128_kernel()
{
    __shared__ int weq[32], wsel[32];
    int b = blockIdx.x, i = threadIdx.x;
    int lane = i & 31, warp = i >> 5;
    unsigned bits = __float_as_uint(g_scoresA[b * NN + i]);
    unsigned ui = (bits & 0x80000000u) ? ~bits : (bits | 0x80000000u);

    unsigned thr = 0;
    #pragma unroll
    for (int bit = 31; bit >= 0; --bit) {
        unsigned trial = thr | (1u << bit);
        int c = __syncthreads_count(ui >= trial);
        if (c >= CAND) thr = trial;
    }
    int isGT = ui > thr;
    int isEQ = (ui == thr);
    int cntGT = __syncthreads_count(isGT);
    int k2 = CAND - cntGT;

    unsigned lmlt = (lane == 0) ? 0u : (0xffffffffu >> (32 - lane));
    unsigned eqm = __ballot_sync(0xffffffffu, isEQ);
    if (lane == 0) weq[warp] = __popc(eqm);
    __syncthreads();
    int eqBefore = __popc(eqm & lmlt);
    #pragma unroll
    for (int w = 0; w < 32; ++w) if (w < warp) eqBefore += weq[w];

    int flag = isGT || (isEQ && eqBefore < k2);
    unsigned sm_ = __ballot_sync(0xffffffffu, flag);
    if (lane == 0) wsel[warp] = __popc(sm_);
    __syncthreads();
    int pos = __popc(sm_ & lmlt);
    #pragma unroll
    for (int w = 0; w < 32; ++w) if (w < warp) pos += wsel[w];

    if (flag) g_cand[b * CAND + pos] = i;
}

// ================= Refine: 3-term bf16 GEMM over gathered candidates =================
// grid (128, 3): blockIdx.x -> (batch, half of 64 cands); blockIdx.y = K-split (256 wide, 8 chunks).
// Writes raw partial D[64 x 256] to g_part (no epilogue).
#define SR_A(buf, term) ((uint32_t)(((buf)*2 + (term)) * 5120))
#define SR_B(buf, term) ((uint32_t)(20480 + ((buf)*2 + (term)) * 20480))
#define SR_BYTES 102400u

__global__ __launch_bounds__(512, 2) void refine_mma(const float* __restrict__ dv)
{
    extern __shared__ char smem[];
    uint32_t sb = smem_u32(smem);
    const int tid = threadIdx.x, wid = tid >> 5, lane = tid & 31;
    const int warpM = wid >> 2, warpN = wid & 3;
    const int batch = blockIdx.x >> 1, half = blockIdx.x & 1;
    const int ks = blockIdx.y;
    const int kbase = ks * 256;

    float acc[8][4];
    #pragma unroll
    for (int j = 0; j < 8; ++j)
        #pragma unroll
        for (int r = 0; r < 4; ++r) acc[j][r] = 0.f;

    const uint32_t a_row_l = (uint32_t)(lane & 15);
    const uint32_t a_k_l   = (uint32_t)(lane >> 4) * 16u;
    const uint32_t b_n_l   = (uint32_t)((lane & 7) + ((lane >> 4) << 3));
    const uint32_t b_k_l   = (uint32_t)((lane >> 3) & 1) * 16u;

    const int ar = tid >> 3, aq = tid & 7;
    const int crow = g_cand[batch * CAND + half * 64 + ar];
    const float* aG = dv + ((size_t)batch * NN + crow) * DD + kbase + aq * 4;
    const uint32_t aStOff = (uint32_t)(ar * 80 + aq * 8);

    { // chunk 0
        float4 v = *(const float4*)aG;
        uint32_t h0,h1,h2,h3,l0,l1,l2,l3;
        split_bf16(v.x,h0,l0); split_bf16(v.y,h1,l1);
        split_bf16(v.z,h2,l2); split_bf16(v.w,h3,l3);
        uint2 hv = { h0 | (h1<<16), h2 | (h3<<16) };
        uint2 lv = { l0 | (l1<<16), l2 | (l3<<16) };
        *(uint2*)(smem + SR_A(0,0) + aStOff) = hv;
        *(uint2*)(smem + SR_A(0,1) + aStOff) = lv;
        #pragma unroll
        for (int i = 0; i < 4; ++i) {
            int idx = i * 512 + tid;
            int kq = idx & 3, n = (idx >> 2) & 255, term = idx >> 10;
            const __nv_bfloat16* src = (term ? g_Blo : g_Bhi) + (size_t)n * DD + kbase + kq * 8;
            cpasync16(sb + SR_B(0, term) + n*80 + kq*16, src);
        }
        cpasync_commit();
        cpasync_wait0();
    }
    __syncthreads();

    for (int c = 0; c < 8; ++c) {
        const int cur = c & 1, nxt = cur ^ 1;
        float4 aReg;
        if (c < 7) {
            const int k0 = kbase + (c + 1) * 32;
            #pragma unroll
            for (int i = 0; i < 4; ++i) {
                int idx = i * 512 + tid;
                int kq = idx & 3, n = (idx >> 2) & 255, term = idx >> 10;
                const __nv_bfloat16* src = (term ? g_Blo : g_Bhi) + (size_t)n * DD + k0 + kq * 8;
                cpasync16(sb + SR_B(nxt, term) + n*80 + kq*16, src);
            }
            cpasync_commit();
            aReg = *(const float4*)(aG + (c + 1) * 32);
        }

        const uint32_t Ah = sb + SR_A(cur,0), Al = sb + SR_A(cur,1);
        const uint32_t Bh = sb + SR_B(cur,0), Bl = sb + SR_B(cur,1);
        #pragma unroll
        for (int kk = 0; kk < 2; ++kk) {
            const uint32_t kb = (uint32_t)(kk * 32);
            uint32_t ah[4], al[4];
            const uint32_t aoff = (uint32_t)(warpM*16 + a_row_l)*80 + kb + a_k_l;
            ldsm4(ah, Ah + aoff);
            ldsm4(al, Al + aoff);
            #pragma unroll
            for (int nt = 0; nt < 4; ++nt) {
                uint32_t bh[4], bl[4];
                const uint32_t boff = (uint32_t)(warpN*64 + nt*16 + b_n_l)*80 + kb + b_k_l;
                ldsm4(bh, Bh + boff);
                ldsm4(bl, Bl + boff);
                float* d0 = acc[nt*2], *d1 = acc[nt*2+1];
                mma_bf16(d0, ah, bh);     mma_bf16(d1, ah, bh+2);
                mma_bf16(d0, ah, bl);     mma_bf16(d1, ah, bl+2);
                mma_bf16(d0, al, bh);     mma_bf16(d1, al, bh+2);
            }
        }

        if (c < 7) {
            uint32_t h0,h1,h2,h3,l0,l1,l2,l3;
            split_bf16(aReg.x,h0,l0); split_bf16(aReg.y,h1,l1);
            split_bf16(aReg.z,h2,l2); split_bf16(aReg.w,h3,l3);
            uint2 hv = { h0 | (h1<<16), h2 | (h3<<16) };
            uint2 lv = { l0 | (l1<<16), l2 | (l3<<16) };
            *(uint2*)(smem + SR_A(nxt,0) + aStOff) = hv;
            *(uint2*)(smem + SR_A(nxt,1) + aStOff) = lv;
            cpasync_wait0();
        }
        __syncthreads();
    }

    // write raw partials
    const int rowG = batch * CAND + half * 64 + warpM * 16 + (lane >> 2);
    #pragma unroll
    for (int j = 0; j < 8; ++j) {
        int n = warpN*64 + j*8 + (lane & 3)*2;
        size_t o  = ((size_t)ks * (BB*CAND) + rowG) * HH + n;
        size_t o2 = ((size_t)ks * (BB*CAND) + rowG + 8) * HH + n;
        *(float2*)&g_part[o]  = make_float2(acc[j][0], acc[j][1]);
        *(float2*)&g_part[o2] = make_float2(acc[j][2], acc[j][3]);
    }
}

// ---------------- reduce partials + exact top-96 among 128 candidates ----------------
__global__ __launch_bounds__(256) void reduce_select(
    const float* __restrict__ W2, const float* __restrict__ b2p,
    float* outIdxF, int writeIdx)
{
    __shared__ float sc[CAND];
    __shared__ int wsel[4];
    const int b = blockIdx.x, tid = threadIdx.x, warp = tid >> 5, lane = tid & 31;
    const float bias2 = b2p[0];

    // 8 warps x 16 iterations: one candidate per warp per iteration
    for (int it = 0; it < 16; ++it) {
        int c = it * 8 + warp;
        float acc = 0.f;
        #pragma unroll
        for (int q = 0; q < 8; ++q) {
            int h = q * 32 + lane;
            size_t base = ((size_t)b * CAND + c) * HH + h;
            float v = g_part[base]
                    + g_part[(size_t)(BB*CAND)*HH + base]
                    + g_part[2*(size_t)(BB*CAND)*HH + base]
                    + g_ctxh[b * HH + h];
            acc += fmaxf(v, 0.f) * W2[h];
        }
        #pragma unroll
        for (int off = 16; off; off >>= 1)
            acc += __shfl_xor_sync(0xffffffffu, acc, off);
        if (lane == 0) sc[c] = 1.f / (1.f + expf(-(acc + bias2)));
    }
    __syncthreads();

    // exact top-96 among 128 (score desc, index asc). cand list is index-sorted.
    int flag = 0;
    if (tid < CAND) {
        float my = sc[tid];
        int rank = 0;
        #pragma unroll 4
        for (int j = 0; j < CAND; ++j) {
            float sj = sc[j];
            rank += (sj > my) || (sj == my && j < tid);
        }
        flag = (rank < KEEP);
    }
    unsigned m = __ballot_sync(0xffffffffu, flag);
    if (lane == 0 && warp < 4) wsel[warp] = __popc(m);
    __syncthreads();
    if (flag) {
        unsigned lmlt = (lane == 0) ? 0u : (0xffffffffu >> (32 - lane));
        int pos = __popc(m & lmlt);
        #pragma unroll
        for (int w = 0; w < 4; ++w) if (w < warp) pos += wsel[w];
        int orig = g_cand[b * CAND + tid];
        g_topk[b * KEEP + pos] = orig;
        if (writeIdx) outIdxF[b * KEEP + pos] = (float)orig;
    }
}

// ---------------- gather selected rows + register token ----------------
__global__ __launch_bounds__(192) void gather_kernel(
    const float* __restrict__ dv, const float* __restrict__ regTok,
    float* __restrict__ out)
{
    int row = blockIdx.x;
    int b = row / (KEEP + 1), k = row % (KEEP + 1);
    const float* src = (k < KEEP)
        ? dv + ((size_t)b * NN + g_topk[b * KEEP + k]) * DD
        : regTok;
    float4 v = ((const float4*)src)[threadIdx.x];
    ((float4*)(out + (size_t)row * DD))[threadIdx.x] = v;
}

extern "C" void kernel_launch(void* const* d_in, const int* in_sizes, int n_in,
                              void* d_out, int out_size)
{
    const float* dv   = (const float*)d_in[0];
    const float* text = (const float*)d_in[1];
    const float* W1   = (const float*)d_in[2];
    const float* b1   = (const float*)d_in[3];
    const float* W2   = (const float*)d_in[4];
    const float* b2   = (const float*)d_in[5];
    const float* regT = (const float*)d_in[6];
    float* out = (float*)d_out;
    (void)in_sizes; (void)n_in;

    static int smem_set = 0;
    if (!smem_set) {
        cudaFuncSetAttribute(scorer_approx, cudaFuncAttributeMaxDynamicSharedMemorySize, SA_BYTES);
        cudaFuncSetAttribute(refine_mma,   cudaFuncAttributeMaxDynamicSharedMemorySize, SR_BYTES);
        smem_set = 1;
    }

    prep_w1<<<DD * HH / 256, 256>>>(W1);
    ctx_kernel<<<BB, 256>>>(text, W1, b1);
    scorer_approx<<<MM / 64, 512, SA_BYTES>>>(dv, W2, b2);
    topk128_kernel<<<BB, 1024>>>();
    refine_mma<<<dim3(BB * 2, KSPLIT), 512, SR_BYTES>>>(dv);

    const int visElems = BB * (KEEP + 1) * DD;
    int writeIdx = (out_size >= visElems + BB * KEEP) ? 1 : 0;
    reduce_select<<<BB, 256>>>(W2, b2, out + visElems, writeIdx);
    gather_kernel<<<BB * (KEEP + 1), 192>>>(dv, regT, out);
}

// round 6
// speedup vs baseline: 2.9721x; 1.0859x over previous
#include <cuda_runtime.h>
#include <cuda_bf16.h>
#include <math.h>
#include <stdint.h>

#define BB 64
#define NN 1024
#define SS 64
#define DD 768
#define HH 256
#define KEEP 96
#define CAND 128
#define MM (BB*NN)

// ---------------- device scratch (no allocations allowed) ----------------
__device__ float          g_ctxh[BB*HH];
__device__ float          g_scoresA[MM];
__device__ int            g_cand[BB*CAND];
__device__ int            g_topk[BB*KEEP];
__device__ float          g_rpart[2][BB*CAND];
__device__ __nv_bfloat16  g_Bhi[HH*DD];
__device__ __nv_bfloat16  g_Blo[HH*DD];

// ---------------- PTX helpers ----------------
__device__ __forceinline__ uint32_t smem_u32(const void* p) {
    uint32_t a;
    asm("{ .reg .u64 t; cvta.to.shared.u64 t, %1; cvt.u32.u64 %0, t; }" : "=r"(a) : "l"(p));
    return a;
}
__device__ __forceinline__ void ldsm4(uint32_t* r, uint32_t addr) {
    asm volatile("ldmatrix.sync.aligned.m8n8.x4.shared.b16 {%0,%1,%2,%3}, [%4];"
                 : "=r"(r[0]), "=r"(r[1]), "=r"(r[2]), "=r"(r[3]) : "r"(addr));
}
__device__ __forceinline__ void mma_bf16(float* d, const uint32_t* a, const uint32_t* b) {
    asm volatile(
        "mma.sync.aligned.m16n8k16.row.col.f32.bf16.bf16.f32 "
        "{%0,%1,%2,%3}, {%4,%5,%6,%7}, {%8,%9}, {%0,%1,%2,%3};"
        : "+f"(d[0]), "+f"(d[1]), "+f"(d[2]), "+f"(d[3])
        : "r"(a[0]), "r"(a[1]), "r"(a[2]), "r"(a[3]), "r"(b[0]), "r"(b[1]));
}
__device__ __forceinline__ void cpasync16(uint32_t dst, const void* src) {
    asm volatile("cp.async.ca.shared.global [%0], [%1], 16;" :: "r"(dst), "l"(src));
}
__device__ __forceinline__ void cpasync_commit() { asm volatile("cp.async.commit_group;"); }
__device__ __forceinline__ void cpasync_wait0()  { asm volatile("cp.async.wait_group 0;"); }

__device__ __forceinline__ void split_bf16(float x, uint32_t& hi_us, uint32_t& lo_us) {
    __nv_bfloat16 h = __float2bfloat16_rn(x);
    float r = x - __bfloat162float(h);
    __nv_bfloat16 l = __float2bfloat16_rn(r);
    hi_us = (uint32_t)__bfloat16_as_ushort(h);
    lo_us = (uint32_t)__bfloat16_as_ushort(l);
}
__device__ __forceinline__ uint32_t bf16_hi(float x) {
    return (uint32_t)__bfloat16_as_ushort(__float2bfloat16_rn(x));
}

// ---------------- Kernel 0: split + transpose W1 visual half ----------------
__global__ __launch_bounds__(256) void prep_w1(const float* __restrict__ W1) {
    int e = blockIdx.x * 256 + threadIdx.x;
    int d = e >> 8, h = e & 255;
    float x = W1[(size_t)d * HH + h];
    uint32_t hi, lo; split_bf16(x, hi, lo);
    g_Bhi[h * DD + d] = __ushort_as_bfloat16((unsigned short)hi);
    g_Blo[h * DD + d] = __ushort_as_bfloat16((unsigned short)lo);
}

// ---------------- Kernel 1: text mean-pool + text half of layer 1 ----------------
__global__ __launch_bounds__(256) void ctx_kernel(
    const float* __restrict__ text, const float* __restrict__ W1,
    const float* __restrict__ b1)
{
    __shared__ float tm[DD];
    int b = blockIdx.x, tid = threadIdx.x;
    for (int d = tid; d < DD; d += 256) {
        const float* p = text + (size_t)b * SS * DD + d;
        float s = 0.f;
        #pragma unroll 8
        for (int j = 0; j < SS; ++j) s += p[(size_t)j * DD];
        tm[d] = s * (1.0f / SS);
    }
    __syncthreads();
    int h = tid;
    float acc = b1[h];
    const float* w = W1 + (size_t)DD * HH + h;
    #pragma unroll 8
    for (int d = 0; d < DD; ++d) acc += tm[d] * w[(size_t)d * HH];
    g_ctxh[b * HH + h] = acc;
}

// ================= Approx scorer: 1-term bf16 HMMA + fused epilogue =================
#define SA_A(buf)  ((uint32_t)((buf)*5120))
#define SA_B(buf)  ((uint32_t)(10240 + (buf)*20480))
#define SA_CTX 51200u
#define SA_W2  52224u
#define SA_PART 53248u
#define SA_BYTES 54272u

__global__ __launch_bounds__(512, 2) void scorer_approx(
    const float* __restrict__ dv, const float* __restrict__ W2,
    const float* __restrict__ b2p)
{
    extern __shared__ char smem[];
    uint32_t sb = smem_u32(smem);
    const int tid = threadIdx.x, wid = tid >> 5, lane = tid & 31;
    const int warpM = wid >> 2, warpN = wid & 3;
    const int row0 = blockIdx.x * 64;
    const int b = blockIdx.x >> 4;

    if (tid < 256) {
        ((float*)(smem + SA_CTX))[tid] = g_ctxh[b * HH + tid];
        ((float*)(smem + SA_W2))[tid]  = W2[tid];
    }

    float acc[8][4];
    #pragma unroll
    for (int j = 0; j < 8; ++j)
        #pragma unroll
        for (int r = 0; r < 4; ++r) acc[j][r] = 0.f;

    const uint32_t a_row_l = (uint32_t)(lane & 15);
    const uint32_t a_k_l   = (uint32_t)(lane >> 4) * 16u;
    const uint32_t b_n_l   = (uint32_t)((lane & 7) + ((lane >> 4) << 3));
    const uint32_t b_k_l   = (uint32_t)((lane >> 3) & 1) * 16u;

    const int ar = tid >> 3, aq = tid & 7;
    const float* aG = dv + (size_t)(row0 + ar) * DD + aq * 4;
    const uint32_t aStOff = (uint32_t)(ar * 80 + aq * 8);

    {
        float4 v = *(const float4*)aG;
        uint2 hv = { bf16_hi(v.x) | (bf16_hi(v.y) << 16),
                     bf16_hi(v.z) | (bf16_hi(v.w) << 16) };
        *(uint2*)(smem + SA_A(0) + aStOff) = hv;
        #pragma unroll
        for (int i = 0; i < 2; ++i) {
            int idx = i * 512 + tid;
            int kq = idx & 3, n = idx >> 2;
            cpasync16(sb + SA_B(0) + n*80 + kq*16, g_Bhi + (size_t)n * DD + kq * 8);
        }
        cpasync_commit();
        cpasync_wait0();
    }
    __syncthreads();

    for (int c = 0; c < 24; ++c) {
        const int cur = c & 1, nxt = cur ^ 1;
        float4 aReg;
        if (c < 23) {
            const int k0 = (c + 1) * 32;
            #pragma unroll
            for (int i = 0; i < 2; ++i) {
                int idx = i * 512 + tid;
                int kq = idx & 3, n = idx >> 2;
                cpasync16(sb + SA_B(nxt) + n*80 + kq*16, g_Bhi + (size_t)n * DD + k0 + kq * 8);
            }
            cpasync_commit();
            aReg = *(const float4*)(aG + k0);
        }

        const uint32_t Ah = sb + SA_A(cur), Bh = sb + SA_B(cur);
        #pragma unroll
        for (int kk = 0; kk < 2; ++kk) {
            const uint32_t kb = (uint32_t)(kk * 32);
            uint32_t ah[4];
            ldsm4(ah, Ah + (uint32_t)(warpM*16 + a_row_l)*80 + kb + a_k_l);
            #pragma unroll
            for (int nt = 0; nt < 4; ++nt) {
                uint32_t bh[4];
                ldsm4(bh, Bh + (uint32_t)(warpN*64 + nt*16 + b_n_l)*80 + kb + b_k_l);
                mma_bf16(acc[nt*2],   ah, bh);
                mma_bf16(acc[nt*2+1], ah, bh+2);
            }
        }

        if (c < 23) {
            uint2 hv = { bf16_hi(aReg.x) | (bf16_hi(aReg.y) << 16),
                         bf16_hi(aReg.z) | (bf16_hi(aReg.w) << 16) };
            *(uint2*)(smem + SA_A(nxt) + aStOff) = hv;
            cpasync_wait0();
        }
        __syncthreads();
    }

    const float* sctx = (const float*)(smem + SA_CTX);
    const float* sw2  = (const float*)(smem + SA_W2);
    float lg0 = 0.f, lg1 = 0.f;
    #pragma unroll
    for (int j = 0; j < 8; ++j) {
        int n = warpN*64 + j*8 + (lane & 3)*2;
        float c0 = sctx[n], c1 = sctx[n+1], w0 = sw2[n], w1 = sw2[n+1];
        lg0 += fmaxf(acc[j][0] + c0, 0.f) * w0 + fmaxf(acc[j][1] + c1, 0.f) * w1;
        lg1 += fmaxf(acc[j][2] + c0, 0.f) * w0 + fmaxf(acc[j][3] + c1, 0.f) * w1;
    }
    lg0 += __shfl_xor_sync(0xffffffffu, lg0, 1);
    lg0 += __shfl_xor_sync(0xffffffffu, lg0, 2);
    lg1 += __shfl_xor_sync(0xffffffffu, lg1, 1);
    lg1 += __shfl_xor_sync(0xffffffffu, lg1, 2);
    float* part = (float*)(smem + SA_PART);
    if ((lane & 3) == 0) {
        int r0 = warpM*16 + (lane >> 2);
        part[r0 * 4 + warpN]       = lg0;
        part[(r0 + 8) * 4 + warpN] = lg1;
    }
    __syncthreads();
    if (tid < 64)
        g_scoresA[row0 + tid] = part[tid*4] + part[tid*4+1] + part[tid*4+2] + part[tid*4+3] + b2p[0];
}

// ---------------- approx top-128: 24-bit binary search ----------------
__global__ __launch_bounds__(1024) void topk128_kernel()
{
    __shared__ int weq[32], wsel[32];
    int b = blockIdx.x, i = threadIdx.x;
    int lane = i & 31, warp = i >> 5;
    unsigned bits = __float_as_uint(g_scoresA[b * NN + i]);
    unsigned ui = (bits & 0x80000000u) ? ~bits : (bits | 0x80000000u);
    ui &= 0xFFFFFF00u;

    unsigned thr = 0;
    #pragma unroll
    for (int bit = 31; bit >= 8; --bit) {
        unsigned trial = thr | (1u << bit);
        int c = __syncthreads_count(ui >= trial);
        if (c >= CAND) thr = trial;
    }
    int isGT = ui > thr;
    int isEQ = (ui == thr);
    int cntGT = __syncthreads_count(isGT);
    int k2 = CAND - cntGT;

    unsigned lmlt = (lane == 0) ? 0u : (0xffffffffu >> (32 - lane));
    unsigned eqm = __ballot_sync(0xffffffffu, isEQ);
    if (lane == 0) weq[warp] = __popc(eqm);
    __syncthreads();
    int eqBefore = __popc(eqm & lmlt);
    #pragma unroll
    for (int w = 0; w < 32; ++w) if (w < warp) eqBefore += weq[w];

    int flag = isGT || (isEQ && eqBefore < k2);
    unsigned sm_ = __ballot_sync(0xffffffffu, flag);
    if (lane == 0) wsel[warp] = __popc(sm_);
    __syncthreads();
    int pos = __popc(sm_ & lmlt);
    #pragma unroll
    for (int w = 0; w < 32; ++w) if (w < warp) pos += wsel[w];

    if (flag) g_cand[b * CAND + pos] = i;
}

// ================= Refine: 3-term bf16 GEMM, N-split halves, fully fused =================
#define RF_A(buf, term) ((uint32_t)(((buf)*2 + (term)) * 5120))
#define RF_B(buf, term) ((uint32_t)(20480 + ((buf)*2 + (term)) * 10240))
#define RF_CTX  61440u
#define RF_W2   61952u
#define RF_PART 62464u
#define RF_BYTES 63488u

__global__ __launch_bounds__(512, 2) void refine_mma(
    const float* __restrict__ dv, const float* __restrict__ W2)
{
    extern __shared__ char smem[];
    uint32_t sb = smem_u32(smem);
    const int tid = threadIdx.x, wid = tid >> 5, lane = tid & 31;
    const int warpM = wid >> 2, warpN = wid & 3;
    const int batch = blockIdx.x >> 2;
    const int half  = (blockIdx.x >> 1) & 1;
    const int nHalf = blockIdx.x & 1;

    if (tid < 128) {
        ((float*)(smem + RF_CTX))[tid] = g_ctxh[batch * HH + nHalf * 128 + tid];
        ((float*)(smem + RF_W2))[tid]  = W2[nHalf * 128 + tid];
    }

    float acc[4][4];
    #pragma unroll
    for (int j = 0; j < 4; ++j)
        #pragma unroll
        for (int r = 0; r < 4; ++r) acc[j][r] = 0.f;

    const uint32_t a_row_l = (uint32_t)(lane & 15);
    const uint32_t a_k_l   = (uint32_t)(lane >> 4) * 16u;
    const uint32_t b_n_l   = (uint32_t)((lane & 7) + ((lane >> 4) << 3));
    const uint32_t b_k_l   = (uint32_t)((lane >> 3) & 1) * 16u;

    const int ar = tid >> 3, aq = tid & 7;
    const int crow = g_cand[batch * CAND + half * 64 + ar];
    const float* aG = dv + ((size_t)batch * NN + crow) * DD + aq * 4;
    const uint32_t aStOff = (uint32_t)(ar * 80 + aq * 8);
    const __nv_bfloat16* BsrcH = g_Bhi + (size_t)nHalf * 128 * DD;
    const __nv_bfloat16* BsrcL = g_Blo + (size_t)nHalf * 128 * DD;

    {
        float4 v = *(const float4*)aG;
        uint32_t h0,h1,h2,h3,l0,l1,l2,l3;
        split_bf16(v.x,h0,l0); split_bf16(v.y,h1,l1);
        split_bf16(v.z,h2,l2); split_bf16(v.w,h3,l3);
        uint2 hv = { h0 | (h1<<16), h2 | (h3<<16) };
        uint2 lv = { l0 | (l1<<16), l2 | (l3<<16) };
        *(uint2*)(smem + RF_A(0,0) + aStOff) = hv;
        *(uint2*)(smem + RF_A(0,1) + aStOff) = lv;
        #pragma unroll
        for (int i = 0; i < 2; ++i) {
            int idx = i * 512 + tid;
            int kq = idx & 3, n = (idx >> 2) & 127, term = idx >> 9;
            const __nv_bfloat16* src = (term ? BsrcL : BsrcH) + (size_t)n * DD + kq * 8;
            cpasync16(sb + RF_B(0, term) + n*80 + kq*16, src);
        }
        cpasync_commit();
        cpasync_wait0();
    }
    __syncthreads();

    for (int c = 0; c < 24; ++c) {
        const int cur = c & 1, nxt = cur ^ 1;
        float4 aReg;
        if (c < 23) {
            const int k0 = (c + 1) * 32;
            #pragma unroll
            for (int i = 0; i < 2; ++i) {
                int idx = i * 512 + tid;
                int kq = idx & 3, n = (idx >> 2) & 127, term = idx >> 9;
                const __nv_bfloat16* src = (term ? BsrcL : BsrcH) + (size_t)n * DD + k0 + kq * 8;
                cpasync16(sb + RF_B(nxt, term) + n*80 + kq*16, src);
            }
            cpasync_commit();
            aReg = *(const float4*)(aG + (c + 1) * 32);
        }

        const uint32_t Ah = sb + RF_A(cur,0), Al = sb + RF_A(cur,1);
        const uint32_t Bh = sb + RF_B(cur,0), Bl = sb + RF_B(cur,1);
        #pragma unroll
        for (int kk = 0; kk < 2; ++kk) {
            const uint32_t kb = (uint32_t)(kk * 32);
            uint32_t ah[4], al[4];
            const uint32_t aoff = (uint32_t)(warpM*16 + a_row_l)*80 + kb + a_k_l;
            ldsm4(ah, Ah + aoff);
            ldsm4(al, Al + aoff);
            #pragma unroll
            for (int nt = 0; nt < 2; ++nt) {
                uint32_t bh[4], bl[4];
                const uint32_t boff = (uint32_t)(warpN*32 + nt*16 + b_n_l)*80 + kb + b_k_l;
                ldsm4(bh, Bh + boff);
                ldsm4(bl, Bl + boff);
                float* d0 = acc[nt*2], *d1 = acc[nt*2+1];
                mma_bf16(d0, ah, bh);     mma_bf16(d1, ah, bh+2);
                mma_bf16(d0, ah, bl);     mma_bf16(d1, ah, bl+2);
                mma_bf16(d0, al, bh);     mma_bf16(d1, al, bh+2);
            }
        }

        if (c < 23) {
            uint32_t h0,h1,h2,h3,l0,l1,l2,l3;
            split_bf16(aReg.x,h0,l0); split_bf16(aReg.y,h1,l1);
            split_bf16(aReg.z,h2,l2); split_bf16(aReg.w,h3,l3);
            uint2 hv = { h0 | (h1<<16), h2 | (h3<<16) };
            uint2 lv = { l0 | (l1<<16), l2 | (l3<<16) };
            *(uint2*)(smem + RF_A(nxt,0) + aStOff) = hv;
            *(uint2*)(smem + RF_A(nxt,1) + aStOff) = lv;
            cpasync_wait0();
        }
        __syncthreads();
    }

    const float* sctx = (const float*)(smem + RF_CTX);
    const float* sw2  = (const float*)(smem + RF_W2);
    float lg0 = 0.f, lg1 = 0.f;
    #pragma unroll
    for (int j = 0; j < 4; ++j) {
        int cl = warpN*32 + j*8 + (lane & 3)*2;
        float c0 = sctx[cl], c1 = sctx[cl+1], w0 = sw2[cl], w1 = sw2[cl+1];
        lg0 += fmaxf(acc[j][0] + c0, 0.f) * w0 + fmaxf(acc[j][1] + c1, 0.f) * w1;
        lg1 += fmaxf(acc[j][2] + c0, 0.f) * w0 + fmaxf(acc[j][3] + c1, 0.f) * w1;
    }
    lg0 += __shfl_xor_sync(0xffffffffu, lg0, 1);
    lg0 += __shfl_xor_sync(0xffffffffu, lg0, 2);
    lg1 += __shfl_xor_sync(0xffffffffu, lg1, 1);
    lg1 += __shfl_xor_sync(0xffffffffu, lg1, 2);
    float* part = (float*)(smem + RF_PART);
    if ((lane & 3) == 0) {
        int r0 = warpM*16 + (lane >> 2);
        part[r0 * 4 + warpN]       = lg0;
        part[(r0 + 8) * 4 + warpN] = lg1;
    }
    __syncthreads();
    if (tid < 64)
        g_rpart[nHalf][batch * CAND + half * 64 + tid] =
            part[tid*4] + part[tid*4+1] + part[tid*4+2] + part[tid*4+3];
}

// ---------------- select: exact top-96 among 128 candidates ----------------
__global__ __launch_bounds__(128) void select_kernel(
    const float* __restrict__ b2p, float* outIdxF, int writeIdx)
{
    __shared__ float sc[CAND];
    __shared__ int wsel[4];
    const int b = blockIdx.x, tid = threadIdx.x, warp = tid >> 5, lane = tid & 31;
    float lg = g_rpart[0][b * CAND + tid] + g_rpart[1][b * CAND + tid] + b2p[0];
    sc[tid] = 1.f / (1.f + expf(-lg));
    __syncthreads();

    float my = sc[tid];
    int rank = 0;
    #pragma unroll 4
    for (int j = 0; j < CAND; ++j) {
        float sj = sc[j];
        rank += (sj > my) || (sj == my && j < tid);
    }
    int flag = (rank < KEEP);
    unsigned m = __ballot_sync(0xffffffffu, flag);
    if (lane == 0) wsel[warp] = __popc(m);
    __syncthreads();
    if (flag) {
        unsigned lmlt = (lane == 0) ? 0u : (0xffffffffu >> (32 - lane));
        int pos = __popc(m & lmlt);
        #pragma unroll
        for (int w = 0; w < 4; ++w) if (w < warp) pos += wsel[w];
        int orig = g_cand[b * CAND + tid];
        g_topk[b * KEEP + pos] = orig;
        if (writeIdx) outIdxF[b * KEEP + pos] = (float)orig;
    }
}

// ---------------- gather: 4 rows per block ----------------
__global__ __launch_bounds__(768) void gather_kernel(
    const float* __restrict__ dv, const float* __restrict__ regTok,
    float* __restrict__ out)
{
    int row = blockIdx.x * 4 + (threadIdx.x / 192);
    int t = threadIdx.x % 192;
    int b = row / (KEEP + 1), k = row % (KEEP + 1);
    const float* src = (k < KEEP)
        ? dv + ((size_t)b * NN + g_topk[b * KEEP + k]) * DD
        : regTok;
    float4 v = ((const float4*)src)[t];
    ((float4*)(out + (size_t)row * DD))[t] = v;
}

extern "C" void kernel_launch(void* const* d_in, const int* in_sizes, int n_in,
                              void* d_out, int out_size)
{
    const float* dv   = (const float*)d_in[0];
    const float* text = (const float*)d_in[1];
    const float* W1   = (const float*)d_in[2];
    const float* b1   = (const float*)d_in[3];
    const float* W2   = (const float*)d_in[4];
    const float* b2   = (const float*)d_in[5];
    const float* regT = (const float*)d_in[6];
    float* out = (float*)d_out;
    (void)in_sizes; (void)n_in;

    static int smem_set = 0;
    if (!smem_set) {
        cudaFuncSetAttribute(scorer_approx, cudaFuncAttributeMaxDynamicSharedMemorySize, SA_BYTES);
        cudaFuncSetAttribute(refine_mma,    cudaFuncAttributeMaxDynamicSharedMemorySize, RF_BYTES);
        smem_set = 1;
    }

    prep_w1<<<DD * HH / 256, 256>>>(W1);
    ctx_kernel<<<BB, 256>>>(text, W1, b1);
    scorer_approx<<<MM / 64, 512, SA_BYTES>>>(dv, W2, b2);
    topk128_kernel<<<BB, 1024>>>();
    refine_mma<<<BB * 4, 512, RF_BYTES>>>(dv, W2);

    const int visElems = BB * (KEEP + 1) * DD;
    int writeIdx = (out_size >= visElems + BB * KEEP) ? 1 : 0;
    select_kernel<<<BB, 128>>>(b2, out + visElems, writeIdx);
    gather_kernel<<<BB * (KEEP + 1) / 4, 768>>>(dv, regT, out);
}

// round 7
// speedup vs baseline: 3.3196x; 1.1169x over previous
#include <cuda_runtime.h>
#include <cuda_bf16.h>
#include <math.h>
#include <stdint.h>

#define BB 64
#define NN 1024
#define SS 64
#define DD 768
#define HH 256
#define KEEP 96
#define CAND 128
#define MM (BB*NN)

// ---------------- device scratch (no allocations allowed) ----------------
__device__ float          g_ctxh[BB*HH];
__device__ float          g_scoresA[MM];
__device__ int            g_cand[BB*CAND];
__device__ int            g_topk[BB*KEEP];
__device__ float          g_rpart[2][BB*CAND];
__device__ __nv_bfloat16  g_Bhi[HH*DD];
__device__ __nv_bfloat16  g_Blo[HH*DD];

// ---------------- PTX helpers ----------------
__device__ __forceinline__ uint32_t smem_u32(const void* p) {
    uint32_t a;
    asm("{ .reg .u64 t; cvta.to.shared.u64 t, %1; cvt.u32.u64 %0, t; }" : "=r"(a) : "l"(p));
    return a;
}
__device__ __forceinline__ void ldsm4(uint32_t* r, uint32_t addr) {
    asm volatile("ldmatrix.sync.aligned.m8n8.x4.shared.b16 {%0,%1,%2,%3}, [%4];"
                 : "=r"(r[0]), "=r"(r[1]), "=r"(r[2]), "=r"(r[3]) : "r"(addr));
}
__device__ __forceinline__ void mma_bf16(float* d, const uint32_t* a, const uint32_t* b) {
    asm volatile(
        "mma.sync.aligned.m16n8k16.row.col.f32.bf16.bf16.f32 "
        "{%0,%1,%2,%3}, {%4,%5,%6,%7}, {%8,%9}, {%0,%1,%2,%3};"
        : "+f"(d[0]), "+f"(d[1]), "+f"(d[2]), "+f"(d[3])
        : "r"(a[0]), "r"(a[1]), "r"(a[2]), "r"(a[3]), "r"(b[0]), "r"(b[1]));
}
__device__ __forceinline__ void cpasync16(uint32_t dst, const void* src) {
    asm volatile("cp.async.ca.shared.global [%0], [%1], 16;" :: "r"(dst), "l"(src));
}
__device__ __forceinline__ void cpasync_commit() { asm volatile("cp.async.commit_group;"); }
__device__ __forceinline__ void cpasync_wait0()  { asm volatile("cp.async.wait_group 0;"); }

__device__ __forceinline__ void split_bf16(float x, uint32_t& hi_us, uint32_t& lo_us) {
    __nv_bfloat16 h = __float2bfloat16_rn(x);
    float r = x - __bfloat162float(h);
    __nv_bfloat16 l = __float2bfloat16_rn(r);
    hi_us = (uint32_t)__bfloat16_as_ushort(h);
    lo_us = (uint32_t)__bfloat16_as_ushort(l);
}
__device__ __forceinline__ uint32_t bf16_hi(float x) {
    return (uint32_t)__bfloat16_as_ushort(__float2bfloat16_rn(x));
}

// ---------------- Kernel 0: fused prep (W1 split/transpose) + ctx ----------------
__global__ __launch_bounds__(256) void prepare_kernel(
    const float* __restrict__ W1, const float* __restrict__ text,
    const float* __restrict__ b1)
{
    if (blockIdx.x < DD * HH / 256) {
        int e = blockIdx.x * 256 + threadIdx.x;
        int d = e >> 8, h = e & 255;
        float x = W1[(size_t)d * HH + h];
        uint32_t hi, lo; split_bf16(x, hi, lo);
        g_Bhi[h * DD + d] = __ushort_as_bfloat16((unsigned short)hi);
        g_Blo[h * DD + d] = __ushort_as_bfloat16((unsigned short)lo);
        return;
    }
    // ctx blocks
    __shared__ float tm[DD];
    int b = blockIdx.x - DD * HH / 256, tid = threadIdx.x;
    for (int d = tid; d < DD; d += 256) {
        const float* p = text + (size_t)b * SS * DD + d;
        float s = 0.f;
        #pragma unroll 8
        for (int j = 0; j < SS; ++j) s += p[(size_t)j * DD];
        tm[d] = s * (1.0f / SS);
    }
    __syncthreads();
    int h = tid;
    float acc = b1[h];
    const float* w = W1 + (size_t)DD * HH + h;
    #pragma unroll 8
    for (int d = 0; d < DD; ++d) acc += tm[d] * w[(size_t)d * HH];
    g_ctxh[b * HH + h] = acc;
}

// ================= Approx scorer: 1-term bf16 HMMA, K-chunks of 64 =================
// Block 512 thr (16 warps 4Mx4N), tile M=64 x N=256. 12 chunks, double-buffered.
// Row pitch 144B (128B data + 16 pad) keeps ldmatrix conflict-free.
#define SA_A(buf)  ((uint32_t)((buf)*9216))
#define SA_B(buf)  ((uint32_t)(18432 + (buf)*36864))
#define SA_CTX 92160u
#define SA_W2  93184u
#define SA_PART 94208u
#define SA_BYTES 95232u

__global__ __launch_bounds__(512, 2) void scorer_approx(
    const float* __restrict__ dv, const float* __restrict__ W2,
    const float* __restrict__ b2p)
{
    extern __shared__ char smem[];
    uint32_t sb = smem_u32(smem);
    const int tid = threadIdx.x, wid = tid >> 5, lane = tid & 31;
    const int warpM = wid >> 2, warpN = wid & 3;
    const int row0 = blockIdx.x * 64;
    const int b = blockIdx.x >> 4;

    if (tid < 256) {
        ((float*)(smem + SA_CTX))[tid] = g_ctxh[b * HH + tid];
        ((float*)(smem + SA_W2))[tid]  = W2[tid];
    }

    float acc[8][4];
    #pragma unroll
    for (int j = 0; j < 8; ++j)
        #pragma unroll
        for (int r = 0; r < 4; ++r) acc[j][r] = 0.f;

    const uint32_t a_row_l = (uint32_t)(lane & 15);
    const uint32_t a_k_l   = (uint32_t)(lane >> 4) * 16u;
    const uint32_t b_n_l   = (uint32_t)((lane & 7) + ((lane >> 4) << 3));
    const uint32_t b_k_l   = (uint32_t)((lane >> 3) & 1) * 16u;

    // A load mapping: 1024 float4 per chunk (64 rows x 16 quads), 2 per thread
    const int ar0 = tid >> 4, ac0 = tid & 15;            // idx = tid
    const int ar1 = (tid + 512) >> 4, ac1 = tid & 15;    // idx = tid + 512
    const float* aG0 = dv + (size_t)(row0 + ar0) * DD + ac0 * 4;
    const float* aG1 = dv + (size_t)(row0 + ar1) * DD + ac1 * 4;
    const uint32_t aSt0 = (uint32_t)(ar0 * 144 + ac0 * 8);
    const uint32_t aSt1 = (uint32_t)(ar1 * 144 + ac1 * 8);

    { // chunk 0
        float4 v0 = *(const float4*)aG0;
        float4 v1 = *(const float4*)aG1;
        uint2 h0 = { bf16_hi(v0.x) | (bf16_hi(v0.y) << 16),
                     bf16_hi(v0.z) | (bf16_hi(v0.w) << 16) };
        uint2 h1 = { bf16_hi(v1.x) | (bf16_hi(v1.y) << 16),
                     bf16_hi(v1.z) | (bf16_hi(v1.w) << 16) };
        *(uint2*)(smem + SA_A(0) + aSt0) = h0;
        *(uint2*)(smem + SA_A(0) + aSt1) = h1;
        #pragma unroll
        for (int i = 0; i < 4; ++i) {
            int idx = i * 512 + tid;            // 0..2047 : 256 rows x 8 quads
            int n = idx >> 3, q = idx & 7;
            cpasync16(sb + SA_B(0) + n*144 + q*16, g_Bhi + (size_t)n * DD + q * 8);
        }
        cpasync_commit();
        cpasync_wait0();
    }
    __syncthreads();

    for (int c = 0; c < 12; ++c) {
        const int cur = c & 1, nxt = cur ^ 1;
        float4 v0, v1;
        if (c < 11) {
            const int k0 = (c + 1) * 64;
            #pragma unroll
            for (int i = 0; i < 4; ++i) {
                int idx = i * 512 + tid;
                int n = idx >> 3, q = idx & 7;
                cpasync16(sb + SA_B(nxt) + n*144 + q*16, g_Bhi + (size_t)n * DD + k0 + q * 8);
            }
            cpasync_commit();
            v0 = *(const float4*)(aG0 + k0);
            v1 = *(const float4*)(aG1 + k0);
        }

        const uint32_t Ah = sb + SA_A(cur), Bh = sb + SA_B(cur);
        #pragma unroll
        for (int kk = 0; kk < 4; ++kk) {
            const uint32_t kb = (uint32_t)(kk * 32);
            uint32_t ah[4];
            ldsm4(ah, Ah + (uint32_t)(warpM*16 + a_row_l)*144 + kb + a_k_l);
            #pragma unroll
            for (int nt = 0; nt < 4; ++nt) {
                uint32_t bh[4];
                ldsm4(bh, Bh + (uint32_t)(warpN*64 + nt*16 + b_n_l)*144 + kb + b_k_l);
                mma_bf16(acc[nt*2],   ah, bh);
                mma_bf16(acc[nt*2+1], ah, bh+2);
            }
        }

        if (c < 11) {
            uint2 h0 = { bf16_hi(v0.x) | (bf16_hi(v0.y) << 16),
                         bf16_hi(v0.z) | (bf16_hi(v0.w) << 16) };
            uint2 h1 = { bf16_hi(v1.x) | (bf16_hi(v1.y) << 16),
                         bf16_hi(v1.z) | (bf16_hi(v1.w) << 16) };
            *(uint2*)(smem + SA_A(nxt) + aSt0) = h0;
            *(uint2*)(smem + SA_A(nxt) + aSt1) = h1;
            cpasync_wait0();
        }
        __syncthreads();
    }

    const float* sctx = (const float*)(smem + SA_CTX);
    const float* sw2  = (const float*)(smem + SA_W2);
    float lg0 = 0.f, lg1 = 0.f;
    #pragma unroll
    for (int j = 0; j < 8; ++j) {
        int n = warpN*64 + j*8 + (lane & 3)*2;
        float c0 = sctx[n], c1 = sctx[n+1], w0 = sw2[n], w1 = sw2[n+1];
        lg0 += fmaxf(acc[j][0] + c0, 0.f) * w0 + fmaxf(acc[j][1] + c1, 0.f) * w1;
        lg1 += fmaxf(acc[j][2] + c0, 0.f) * w0 + fmaxf(acc[j][3] + c1, 0.f) * w1;
    }
    lg0 += __shfl_xor_sync(0xffffffffu, lg0, 1);
    lg0 += __shfl_xor_sync(0xffffffffu, lg0, 2);
    lg1 += __shfl_xor_sync(0xffffffffu, lg1, 1);
    lg1 += __shfl_xor_sync(0xffffffffu, lg1, 2);
    float* part = (float*)(smem + SA_PART);
    if ((lane & 3) == 0) {
        int r0 = warpM*16 + (lane >> 2);
        part[r0 * 4 + warpN]       = lg0;
        part[(r0 + 8) * 4 + warpN] = lg1;
    }
    __syncthreads();
    if (tid < 64)
        g_scoresA[row0 + tid] = part[tid*4] + part[tid*4+1] + part[tid*4+2] + part[tid*4+3] + b2p[0];
}

// ---------------- approx top-128: 24-bit binary search ----------------
__global__ __launch_bounds__(1024) void topk128_kernel()
{
    __shared__ int weq[32], wsel[32];
    int b = blockIdx.x, i = threadIdx.x;
    int lane = i & 31, warp = i >> 5;
    unsigned bits = __float_as_uint(g_scoresA[b * NN + i]);
    unsigned ui = (bits & 0x80000000u) ? ~bits : (bits | 0x80000000u);
    ui &= 0xFFFFFF00u;

    unsigned thr = 0;
    #pragma unroll
    for (int bit = 31; bit >= 8; --bit) {
        unsigned trial = thr | (1u << bit);
        int c = __syncthreads_count(ui >= trial);
        if (c >= CAND) thr = trial;
    }
    int isGT = ui > thr;
    int isEQ = (ui == thr);
    int cntGT = __syncthreads_count(isGT);
    int k2 = CAND - cntGT;

    unsigned lmlt = (lane == 0) ? 0u : (0xffffffffu >> (32 - lane));
    unsigned eqm = __ballot_sync(0xffffffffu, isEQ);
    if (lane == 0) weq[warp] = __popc(eqm);
    __syncthreads();
    int eqBefore = __popc(eqm & lmlt);
    #pragma unroll
    for (int w = 0; w < 32; ++w) if (w < warp) eqBefore += weq[w];

    int flag = isGT || (isEQ && eqBefore < k2);
    unsigned sm_ = __ballot_sync(0xffffffffu, flag);
    if (lane == 0) wsel[warp] = __popc(sm_);
    __syncthreads();
    int pos = __popc(sm_ & lmlt);
    #pragma unroll
    for (int w = 0; w < 32; ++w) if (w < warp) pos += wsel[w];

    if (flag) g_cand[b * CAND + pos] = i;
}

// ================= Refine: 3-term bf16 GEMM, N-split halves, fully fused =================
#define RF_A(buf, term) ((uint32_t)(((buf)*2 + (term)) * 5120))
#define RF_B(buf, term) ((uint32_t)(20480 + ((buf)*2 + (term)) * 10240))
#define RF_CTX  61440u
#define RF_W2   61952u
#define RF_PART 62464u
#define RF_BYTES 63488u

__global__ __launch_bounds__(512, 2) void refine_mma(
    const float* __restrict__ dv, const float* __restrict__ W2)
{
    extern __shared__ char smem[];
    uint32_t sb = smem_u32(smem);
    const int tid = threadIdx.x, wid = tid >> 5, lane = tid & 31;
    const int warpM = wid >> 2, warpN = wid & 3;
    const int batch = blockIdx.x >> 2;
    const int half  = (blockIdx.x >> 1) & 1;
    const int nHalf = blockIdx.x & 1;

    if (tid < 128) {
        ((float*)(smem + RF_CTX))[tid] = g_ctxh[batch * HH + nHalf * 128 + tid];
        ((float*)(smem + RF_W2))[tid]  = W2[nHalf * 128 + tid];
    }

    float acc[4][4];
    #pragma unroll
    for (int j = 0; j < 4; ++j)
        #pragma unroll
        for (int r = 0; r < 4; ++r) acc[j][r] = 0.f;

    const uint32_t a_row_l = (uint32_t)(lane & 15);
    const uint32_t a_k_l   = (uint32_t)(lane >> 4) * 16u;
    const uint32_t b_n_l   = (uint32_t)((lane & 7) + ((lane >> 4) << 3));
    const uint32_t b_k_l   = (uint32_t)((lane >> 3) & 1) * 16u;

    const int ar = tid >> 3, aq = tid & 7;
    const int crow = g_cand[batch * CAND + half * 64 + ar];
    const float* aG = dv + ((size_t)batch * NN + crow) * DD + aq * 4;
    const uint32_t aStOff = (uint32_t)(ar * 80 + aq * 8);
    const __nv_bfloat16* BsrcH = g_Bhi + (size_t)nHalf * 128 * DD;
    const __nv_bfloat16* BsrcL = g_Blo + (size_t)nHalf * 128 * DD;

    {
        float4 v = *(const float4*)aG;
        uint32_t h0,h1,h2,h3,l0,l1,l2,l3;
        split_bf16(v.x,h0,l0); split_bf16(v.y,h1,l1);
        split_bf16(v.z,h2,l2); split_bf16(v.w,h3,l3);
        uint2 hv = { h0 | (h1<<16), h2 | (h3<<16) };
        uint2 lv = { l0 | (l1<<16), l2 | (l3<<16) };
        *(uint2*)(smem + RF_A(0,0) + aStOff) = hv;
        *(uint2*)(smem + RF_A(0,1) + aStOff) = lv;
        #pragma unroll
        for (int i = 0; i < 2; ++i) {
            int idx = i * 512 + tid;
            int kq = idx & 3, n = (idx >> 2) & 127, term = idx >> 9;
            const __nv_bfloat16* src = (term ? BsrcL : BsrcH) + (size_t)n * DD + kq * 8;
            cpasync16(sb + RF_B(0, term) + n*80 + kq*16, src);
        }
        cpasync_commit();
        cpasync_wait0();
    }
    __syncthreads();

    for (int c = 0; c < 24; ++c) {
        const int cur = c & 1, nxt = cur ^ 1;
        float4 aReg;
        if (c < 23) {
            const int k0 = (c + 1) * 32;
            #pragma unroll
            for (int i = 0; i < 2; ++i) {
                int idx = i * 512 + tid;
                int kq = idx & 3, n = (idx >> 2) & 127, term = idx >> 9;
                const __nv_bfloat16* src = (term ? BsrcL : BsrcH) + (size_t)n * DD + k0 + kq * 8;
                cpasync16(sb + RF_B(nxt, term) + n*80 + kq*16, src);
            }
            cpasync_commit();
            aReg = *(const float4*)(aG + (c + 1) * 32);
        }

        const uint32_t Ah = sb + RF_A(cur,0), Al = sb + RF_A(cur,1);
        const uint32_t Bh = sb + RF_B(cur,0), Bl = sb + RF_B(cur,1);
        #pragma unroll
        for (int kk = 0; kk < 2; ++kk) {
            const uint32_t kb = (uint32_t)(kk * 32);
            uint32_t ah[4], al[4];
            const uint32_t aoff = (uint32_t)(warpM*16 + a_row_l)*80 + kb + a_k_l;
            ldsm4(ah, Ah + aoff);
            ldsm4(al, Al + aoff);
            #pragma unroll
            for (int nt = 0; nt < 2; ++nt) {
                uint32_t bh[4], bl[4];
                const uint32_t boff = (uint32_t)(warpN*32 + nt*16 + b_n_l)*80 + kb + b_k_l;
                ldsm4(bh, Bh + boff);
                ldsm4(bl, Bl + boff);
                float* d0 = acc[nt*2], *d1 = acc[nt*2+1];
                mma_bf16(d0, ah, bh);     mma_bf16(d1, ah, bh+2);
                mma_bf16(d0, ah, bl);     mma_bf16(d1, ah, bl+2);
                mma_bf16(d0, al, bh);     mma_bf16(d1, al, bh+2);
            }
        }

        if (c < 23) {
            uint32_t h0,h1,h2,h3,l0,l1,l2,l3;
            split_bf16(aReg.x,h0,l0); split_bf16(aReg.y,h1,l1);
            split_bf16(aReg.z,h2,l2); split_bf16(aReg.w,h3,l3);
            uint2 hv = { h0 | (h1<<16), h2 | (h3<<16) };
            uint2 lv = { l0 | (l1<<16), l2 | (l3<<16) };
            *(uint2*)(smem + RF_A(nxt,0) + aStOff) = hv;
            *(uint2*)(smem + RF_A(nxt,1) + aStOff) = lv;
            cpasync_wait0();
        }
        __syncthreads();
    }

    const float* sctx = (const float*)(smem + RF_CTX);
    const float* sw2  = (const float*)(smem + RF_W2);
    float lg0 = 0.f, lg1 = 0.f;
    #pragma unroll
    for (int j = 0; j < 4; ++j) {
        int cl = warpN*32 + j*8 + (lane & 3)*2;
        float c0 = sctx[cl], c1 = sctx[cl+1], w0 = sw2[cl], w1 = sw2[cl+1];
        lg0 += fmaxf(acc[j][0] + c0, 0.f) * w0 + fmaxf(acc[j][1] + c1, 0.f) * w1;
        lg1 += fmaxf(acc[j][2] + c0, 0.f) * w0 + fmaxf(acc[j][3] + c1, 0.f) * w1;
    }
    lg0 += __shfl_xor_sync(0xffffffffu, lg0, 1);
    lg0 += __shfl_xor_sync(0xffffffffu, lg0, 2);
    lg1 += __shfl_xor_sync(0xffffffffu, lg1, 1);
    lg1 += __shfl_xor_sync(0xffffffffu, lg1, 2);
    float* part = (float*)(smem + RF_PART);
    if ((lane & 3) == 0) {
        int r0 = warpM*16 + (lane >> 2);
        part[r0 * 4 + warpN]       = lg0;
        part[(r0 + 8) * 4 + warpN] = lg1;
    }
    __syncthreads();
    if (tid < 64)
        g_rpart[nHalf][batch * CAND + half * 64 + tid] =
            part[tid*4] + part[tid*4+1] + part[tid*4+2] + part[tid*4+3];
}

// ---------------- select: exact top-96 among 128 candidates ----------------
__global__ __launch_bounds__(128) void select_kernel(
    const float* __restrict__ b2p, float* outIdxF, int writeIdx)
{
    __shared__ float sc[CAND];
    __shared__ int wsel[4];
    const int b = blockIdx.x, tid = threadIdx.x, warp = tid >> 5, lane = tid & 31;
    float lg = g_rpart[0][b * CAND + tid] + g_rpart[1][b * CAND + tid] + b2p[0];
    sc[tid] = 1.f / (1.f + expf(-lg));
    __syncthreads();

    float my = sc[tid];
    int rank = 0;
    #pragma unroll 4
    for (int j = 0; j < CAND; ++j) {
        float sj = sc[j];
        rank += (sj > my) || (sj == my && j < tid);
    }
    int flag = (rank < KEEP);
    unsigned m = __ballot_sync(0xffffffffu, flag);
    if (lane == 0) wsel[warp] = __popc(m);
    __syncthreads();
    if (flag) {
        unsigned lmlt = (lane == 0) ? 0u : (0xffffffffu >> (32 - lane));
        int pos = __popc(m & lmlt);
        #pragma unroll
        for (int w = 0; w < 4; ++w) if (w < warp) pos += wsel[w];
        int orig = g_cand[b * CAND + tid];
        g_topk[b * KEEP + pos] = orig;
        if (writeIdx) outIdxF[b * KEEP + pos] = (float)orig;
    }
}

// ---------------- gather: 4 rows per block ----------------
__global__ __launch_bounds__(768) void gather_kernel(
    const float* __restrict__ dv, const float* __restrict__ regTok,
    float* __restrict__ out)
{
    int row = blockIdx.x * 4 + (threadIdx.x / 192);
    int t = threadIdx.x % 192;
    int b = row / (KEEP + 1), k = row % (KEEP + 1);
    const float* src = (k < KEEP)
        ? dv + ((size_t)b * NN + g_topk[b * KEEP + k]) * DD
        : regTok;
    float4 v = ((const float4*)src)[t];
    ((float4*)(out + (size_t)row * DD))[t] = v;
}

extern "C" void kernel_launch(void* const* d_in, const int* in_sizes, int n_in,
                              void* d_out, int out_size)
{
    const float* dv   = (const float*)d_in[0];
    const float* text = (const float*)d_in[1];
    const float* W1   = (const float*)d_in[2];
    const float* b1   = (const float*)d_in[3];
    const float* W2   = (const float*)d_in[4];
    const float* b2   = (const float*)d_in[5];
    const float* regT = (const float*)d_in[6];
    float* out = (float*)d_out;
    (void)in_sizes; (void)n_in;

    static int smem_set = 0;
    if (!smem_set) {
        cudaFuncSetAttribute(scorer_approx, cudaFuncAttributeMaxDynamicSharedMemorySize, SA_BYTES);
        cudaFuncSetAttribute(refine_mma,    cudaFuncAttributeMaxDynamicSharedMemorySize, RF_BYTES);
        smem_set = 1;
    }

    prepare_kernel<<<DD * HH / 256 + BB, 256>>>(W1, text, b1);
    scorer_approx<<<MM / 64, 512, SA_BYTES>>>(dv, W2, b2);
    topk128_kernel<<<BB, 1024>>>();
    refine_mma<<<BB * 4, 512, RF_BYTES>>>(dv, W2);

    const int visElems = BB * (KEEP + 1) * DD;
    int writeIdx = (out_size >= visElems + BB * KEEP) ? 1 : 0;
    select_kernel<<<BB, 128>>>(b2, out + visElems, writeIdx);
    gather_kernel<<<BB * (KEEP + 1) / 4, 768>>>(dv, regT, out);
}